// round 14
// baseline (speedup 1.0000x reference)
#include <cuda_runtime.h>
#include <cuda_bf16.h>
#include <mma.h>
#include <math.h>

using namespace nvcuda;

#define L_SEQ   4096
#define NROWS   8192          // BSZ * L
#define DMODEL  192
#define NSTATE  16
#define NCH     64
#define CSZ     64

// ---------------- fp32 scratch ------------------------------------------------
__device__ float g_xdbl[2][NROWS * 44];           // dt(12)|B(16)|C(16)
__device__ float g_dt  [2][NROWS * DMODEL];
__device__ float g_hend [2][2 * NCH * DMODEL * NSTATE];
__device__ float g_sumdt[2][2 * NCH * DMODEL];
__device__ float g_hinit[2][2 * NCH * DMODEL * NSTATE];
__device__ float g_mo  [NROWS * DMODEL];          // mamba out fp32
__device__ float g_sg  [NROWS * DMODEL];          // SGFN out fp32

// ---------------- bf16 activations ---------------------------------------------
__device__ __nv_bfloat16 g_xf_bf [NROWS * DMODEL];
__device__ __nv_bfloat16 g_xz_bf [NROWS * 768];   // [xm0|z0|xm1|z1]
__device__ __nv_bfloat16 g_xmc_bf[2][NROWS * DMODEL];
__device__ __nv_bfloat16 g_yg_bf [NROWS * 384];
__device__ __nv_bfloat16 g_mo_bf [NROWS * DMODEL];
__device__ __nv_bfloat16 g_t_bf  [NROWS * 768];
__device__ __nv_bfloat16 g_g_bf  [NROWS * 384];

// ---------------- bf16 packed weights ------------------------------------------
__device__ __nv_bfloat16 wb_in  [768 * 192];      // [in_w0 ; in_w1] along N
__device__ __nv_bfloat16 wb_xp  [2 * 44 * 192];
__device__ __nv_bfloat16 wb_out [192 * 384];      // [out_w0 | out_w1] along K
__device__ __nv_bfloat16 wb_c1  [768 * 192];
__device__ __nv_bfloat16 wb_c2  [192 * 384];

__device__ __forceinline__ float sigmoidf_(float v) { return 1.f / (1.f + __expf(-v)); }

// ---------------- weight pack -> bf16 ------------------------------------------
#define PS1 147456
#define PS2 16896
#define PS3 73728
#define PS4 147456
#define PS5 73728
#define PACK_TOTAL (PS1 + PS2 + PS3 + PS4 + PS5)
__global__ void hm_pack_kernel(const float* __restrict__ in_w0, const float* __restrict__ in_w1,
                               const float* __restrict__ xp0, const float* __restrict__ xp1,
                               const float* __restrict__ ow0, const float* __restrict__ ow1,
                               const float* __restrict__ c1w, const float* __restrict__ c2w) {
    int i = blockIdx.x * 256 + threadIdx.x;
    if (i >= PACK_TOTAL) return;
    if (i < PS1) {
        int n = i / 192, k = i % 192;
        wb_in[i] = __float2bfloat16(n < 384 ? in_w0[n * 192 + k] : in_w1[(n - 384) * 192 + k]);
        return;
    }
    i -= PS1;
    if (i < PS2) {
        int z = i / (44 * 192), r = i % (44 * 192);
        wb_xp[i] = __float2bfloat16(z ? xp1[r] : xp0[r]);
        return;
    }
    i -= PS2;
    if (i < PS3) {
        int e = i / 384, k = i % 384;
        wb_out[i] = __float2bfloat16(k < 192 ? ow0[e * 192 + k] : ow1[e * 192 + k - 192]);
        return;
    }
    i -= PS3;
    if (i < PS4) { wb_c1[i] = __float2bfloat16(c1w[i]); return; }
    i -= PS4;
    wb_c2[i] = __float2bfloat16(c2w[i]);
}

// ---------------- LayerNorm over channels -> bf16 ------------------------------
__global__ void __launch_bounds__(256)
hm_ln_kernel(const float* __restrict__ x,
             const float* __restrict__ w,
             const float* __restrict__ b) {
    __shared__ float tile[DMODEL][33];
    __shared__ float mu_s[32], rs_s[32];
    int bb = blockIdx.y;
    int l0 = blockIdx.x * 32;
    int tl = threadIdx.x & 31, tg = threadIdx.x >> 5;
    for (int c = tg; c < DMODEL; c += 8)
        tile[c][tl] = x[((size_t)(bb * DMODEL + c) << 12) + l0 + tl];
    __syncthreads();
    int l = threadIdx.x >> 3, i = threadIdx.x & 7;
    float s = 0.f, q = 0.f;
    for (int c = i; c < DMODEL; c += 8) {
        float v = tile[c][l];
        s += v; q += v * v;
    }
    #pragma unroll
    for (int o = 4; o; o >>= 1) {
        s += __shfl_down_sync(0xffffffff, s, o, 8);
        q += __shfl_down_sync(0xffffffff, q, o, 8);
    }
    if (i == 0) {
        float mu = s * (1.f / DMODEL);
        float var = q * (1.f / DMODEL) - mu * mu;
        mu_s[l] = mu;
        rs_s[l] = rsqrtf(var + 1e-5f);
    }
    __syncthreads();
    for (int idx = threadIdx.x; idx < 32 * DMODEL; idx += 256) {
        int ll = idx / DMODEL, c = idx % DMODEL;
        float v = tile[c][ll];
        g_xf_bf[(size_t)((bb << 12) + l0 + ll) * DMODEL + c] =
            __float2bfloat16((v - mu_s[ll]) * rs_s[ll] * w[c] + b[c]);
    }
}

// ---------------- bf16 cp.async tensor-core GEMM (BM=128, 8 warps of 32x32) ----
#define GBM 128
#define GBN 64
#define GBK 64
#define GLD 72
#define GSMEM (2 * (GBM + GBN) * GLD * 2)   // 55296 bytes

__device__ __forceinline__ void cp16(void* dst, const void* src, int bytes) {
    unsigned d = (unsigned)__cvta_generic_to_shared(dst);
    asm volatile("cp.async.cg.shared.global [%0], [%1], 16, %2;" :: "r"(d), "l"(src), "r"(bytes));
}

__global__ void __launch_bounds__(256, 4)
hm_gemm_bf16(const __nv_bfloat16* __restrict__ A,
             const __nv_bfloat16* __restrict__ W,
             const __nv_bfloat16* __restrict__ Aalt,
             const __nv_bfloat16* __restrict__ Walt,
             float* __restrict__ Calt,
             const float* __restrict__ bias,
             const float* __restrict__ scale,
             float* __restrict__ C,
             __nv_bfloat16* __restrict__ Cb,
             int lda, int ldc, int N, int K) {
    extern __shared__ __align__(16) __nv_bfloat16 sm[];
    __nv_bfloat16* sA = sm;                        // 2 stages x 128 x GLD
    __nv_bfloat16* sB = sm + 2 * GBM * GLD;        // 2 stages x 64 x GLD

    if (blockIdx.z) { A = Aalt; W = Walt; C = Calt; Cb = nullptr; }

    int tid = threadIdx.x;
    int wid = tid >> 5;
    int wr = wid >> 1, wc = wid & 1;               // 4x2 warps, each 32x32
    int row0 = blockIdx.y * GBM;
    int n0 = blockIdx.x * GBN;

    wmma::fragment<wmma::accumulator, 16, 16, 16, float> fc[2][2];
    #pragma unroll
    for (int i = 0; i < 2; i++)
        #pragma unroll
        for (int j = 0; j < 2; j++)
            wmma::fill_fragment(fc[i][j], 0.f);

    int nk = K / GBK;
    {
        #pragma unroll
        for (int i = 0; i < 4; i++) {
            int idx = tid + i * 256;               // 0..1023
            int r = idx >> 3, ch = (idx & 7) * 8;
            cp16(sA + r * GLD + ch, A + (size_t)(row0 + r) * lda + ch, 16);
        }
        #pragma unroll
        for (int i = 0; i < 2; i++) {
            int idx = tid + i * 256;               // 0..511
            int r = idx >> 3, ch = (idx & 7) * 8;
            int n = n0 + r;
            const __nv_bfloat16* src = W + (size_t)(n < N ? n : 0) * K + ch;
            cp16(sB + r * GLD + ch, src, n < N ? 16 : 0);
        }
        asm volatile("cp.async.commit_group;");
    }

    for (int kt = 0; kt < nk; kt++) {
        int cur = kt & 1;
        bool more = (kt + 1 < nk);
        if (more) {
            int nxt = cur ^ 1;
            int k0 = (kt + 1) * GBK;
            #pragma unroll
            for (int i = 0; i < 4; i++) {
                int idx = tid + i * 256;
                int r = idx >> 3, ch = (idx & 7) * 8;
                cp16(sA + nxt * GBM * GLD + r * GLD + ch,
                     A + (size_t)(row0 + r) * lda + k0 + ch, 16);
            }
            #pragma unroll
            for (int i = 0; i < 2; i++) {
                int idx = tid + i * 256;
                int r = idx >> 3, ch = (idx & 7) * 8;
                int n = n0 + r;
                const __nv_bfloat16* src = W + (size_t)(n < N ? n : 0) * K + k0 + ch;
                cp16(sB + nxt * GBN * GLD + r * GLD + ch, src, n < N ? 16 : 0);
            }
            asm volatile("cp.async.commit_group;");
            asm volatile("cp.async.wait_group 1;");
        } else {
            asm volatile("cp.async.wait_group 0;");
        }
        __syncthreads();
        const __nv_bfloat16* cA = sA + cur * GBM * GLD;
        const __nv_bfloat16* cB = sB + cur * GBN * GLD;
        #pragma unroll
        for (int ks = 0; ks < 4; ks++) {
            wmma::fragment<wmma::matrix_a, 16, 16, 16, __nv_bfloat16, wmma::row_major> fa[2];
            wmma::fragment<wmma::matrix_b, 16, 16, 16, __nv_bfloat16, wmma::col_major> fb[2];
            #pragma unroll
            for (int i = 0; i < 2; i++)
                wmma::load_matrix_sync(fa[i], cA + (wr * 32 + i * 16) * GLD + ks * 16, GLD);
            #pragma unroll
            for (int j = 0; j < 2; j++)
                wmma::load_matrix_sync(fb[j], cB + (wc * 32 + j * 16) * GLD + ks * 16, GLD);
            #pragma unroll
            for (int i = 0; i < 2; i++)
                #pragma unroll
                for (int j = 0; j < 2; j++)
                    wmma::mma_sync(fc[i][j], fa[i], fb[j], fc[i][j]);
        }
        __syncthreads();
    }

    float* stage = (float*)sm;                     // 128 x 68 fp32
    #pragma unroll
    for (int i = 0; i < 2; i++)
        #pragma unroll
        for (int j = 0; j < 2; j++)
            wmma::store_matrix_sync(stage + (wr * 32 + i * 16) * 68 + wc * 32 + j * 16,
                                    fc[i][j], 68, wmma::mem_row_major);
    __syncthreads();
    float sc = scale ? *scale : 1.f;
    for (int e = tid; e < GBM * GBN; e += 256) {
        int m = e >> 6, n = e & 63;
        int col = n0 + n;
        if (col >= N) continue;
        float v = stage[m * 68 + n] * sc;
        if (bias) v += bias[col];
        size_t o = (size_t)(row0 + m) * ldc + col;
        if (C) C[o] = v;
        if (Cb) Cb[o] = __float2bfloat16(v);
    }
}

// ---------------- dt projection (K=12, SIMT, dual via z) ------------------------
__global__ void hm_dt_kernel(const float* __restrict__ A0, const float* __restrict__ W0,
                             const float* __restrict__ b0, float* __restrict__ C0,
                             const float* __restrict__ A1, const float* __restrict__ W1,
                             const float* __restrict__ b1, float* __restrict__ C1) {
    const float* A = blockIdx.z ? A1 : A0;
    const float* W = blockIdx.z ? W1 : W0;
    const float* bias = blockIdx.z ? b1 : b0;
    float* C = blockIdx.z ? C1 : C0;
    const int lda = 44, ldc = DMODEL, N = DMODEL, K = 12;
    __shared__ float As[16][65];
    __shared__ float Ws[16][65];
    int tid = threadIdx.x;
    int tx = tid & 15, ty = tid >> 4;
    int row0 = blockIdx.y * 64;
    int n0 = blockIdx.x * 64;
    float acc[4][4] = {};
    {
        #pragma unroll
        for (int i = 0; i < 4; i++) {
            int li = tid + i * 256;
            int m = li >> 4, k = li & 15;
            As[k][m] = (k < K) ? A[(size_t)(row0 + m) * lda + k] : 0.f;
            int wrow = n0 + m;
            Ws[k][m] = (wrow < N && k < K) ? W[(size_t)wrow * K + k] : 0.f;
        }
        __syncthreads();
        #pragma unroll
        for (int kk = 0; kk < 12; kk++) {
            float a[4], w[4];
            #pragma unroll
            for (int i = 0; i < 4; i++) a[i] = As[kk][ty * 4 + i];
            #pragma unroll
            for (int j = 0; j < 4; j++) w[j] = Ws[kk][tx * 4 + j];
            #pragma unroll
            for (int i = 0; i < 4; i++)
                #pragma unroll
                for (int j = 0; j < 4; j++)
                    acc[i][j] += a[i] * w[j];
        }
    }
    #pragma unroll
    for (int i = 0; i < 4; i++) {
        #pragma unroll
        for (int j = 0; j < 4; j++) {
            int col = n0 + tx * 4 + j;
            if (col >= N) continue;
            float v = acc[i][j] + bias[col];
            v = (v > 20.f) ? v : log1pf(__expf(v));
            C[(size_t)(row0 + ty * 4 + i) * ldc + col] = v;
        }
    }
}

// ---------------- conv1d + silu, 2 rows/thread sliding window -------------------
__global__ void hm_conv1d_kernel(const float* __restrict__ cw0, const float* __restrict__ cb0,
                                 const float* __restrict__ cw1, const float* __restrict__ cb1) {
    int pr = blockIdx.x;                  // 4096 blocks
    int bb = pr >> 11, l0 = (pr & 2047) << 1;   // rows l0, l0+1
    int t = threadIdx.x;                  // 384
    int d = t % DMODEL, dir = t / DMODEL;
    const float* cw = dir ? cw1 : cw0;
    float w0 = cw[d * 4], w1 = cw[d * 4 + 1], w2 = cw[d * 4 + 2], w3 = cw[d * 4 + 3];
    float bv = dir ? cb1[d] : cb0[d];
    int col = dir * 384 + d;
    float v[5];
    float a0, a1;
    if (!dir) {
        #pragma unroll
        for (int k = 0; k < 5; k++) {
            int ls = l0 - 3 + k;
            v[k] = (ls >= 0)
                ? __bfloat162float(g_xz_bf[(size_t)((bb << 12) + ls) * 768 + col]) : 0.f;
        }
        a0 = bv + w0 * v[0] + w1 * v[1] + w2 * v[2] + w3 * v[3];
        a1 = bv + w0 * v[1] + w1 * v[2] + w2 * v[3] + w3 * v[4];
    } else {
        #pragma unroll
        for (int k = 0; k < 5; k++) {
            int ls = l0 + k;
            v[k] = (ls < L_SEQ)
                ? __bfloat162float(g_xz_bf[(size_t)((bb << 12) + ls) * 768 + col]) : 0.f;
        }
        a0 = bv + w3 * v[0] + w2 * v[1] + w1 * v[2] + w0 * v[3];
        a1 = bv + w3 * v[1] + w2 * v[2] + w1 * v[3] + w0 * v[4];
    }
    size_t o = (size_t)((bb << 12) + l0) * DMODEL + d;
    g_xmc_bf[dir][o] = __float2bfloat16(a0 * sigmoidf_(a0));
    g_xmc_bf[dir][o + DMODEL] = __float2bfloat16(a1 * sigmoidf_(a1));
}

// ---------------- chunked selective scan ----------------------------------------
__global__ void hm_scanA_kernel(const float* __restrict__ A_log0,
                                const float* __restrict__ A_log1) {
    int c = blockIdx.x;
    int dir = blockIdx.y >> 1, bb = blockIdx.y & 1;
    int d = threadIdx.x;                  // 192
    __shared__ float Bsm[CSZ * NSTATE];
    const float* xdbl = g_xdbl[dir];
    for (int idx = d; idx < CSZ * NSTATE; idx += DMODEL) {
        int i = idx >> 4, n = idx & 15;
        int s = c * CSZ + i;
        int l = dir ? (L_SEQ - 1 - s) : s;
        Bsm[idx] = xdbl[(size_t)((bb << 12) + l) * 44 + 12 + n];
    }
    __syncthreads();
    const float* A_log = dir ? A_log1 : A_log0;
    float an[NSTATE];
    bool fast = true;
    #pragma unroll
    for (int n = 0; n < NSTATE; n++) {
        an[n] = -__expf(A_log[d * NSTATE + n]);
        fast = fast && (fabsf(an[n] + (float)(n + 1)) < 1e-3f * (n + 1));
    }
    float h[NSTATE];
    #pragma unroll
    for (int n = 0; n < NSTATE; n++) h[n] = 0.f;
    float sd = 0.f;
    const float* dtp = g_dt[dir];
    const __nv_bfloat16* xp = g_xmc_bf[dir];
    if (fast) {
        for (int i = 0; i < CSZ; i++) {
            int s = c * CSZ + i;
            int l = dir ? (L_SEQ - 1 - s) : s;
            size_t ro = (size_t)((bb << 12) + l) * DMODEL + d;
            float dtv = dtp[ro], xv = __bfloat162float(xp[ro]);
            sd += dtv;
            float dx = dtv * xv;
            float e1 = __expf(-dtv);
            float e2 = e1 * e1;
            float pa = e1, pb = e2;
            h[0] = pa * h[0] + dx * Bsm[i * NSTATE];
            h[1] = pb * h[1] + dx * Bsm[i * NSTATE + 1];
            #pragma unroll
            for (int n = 2; n < NSTATE; n += 2) {
                pa *= e2; pb *= e2;
                h[n]     = pa * h[n]     + dx * Bsm[i * NSTATE + n];
                h[n + 1] = pb * h[n + 1] + dx * Bsm[i * NSTATE + n + 1];
            }
        }
    } else {
        for (int i = 0; i < CSZ; i++) {
            int s = c * CSZ + i;
            int l = dir ? (L_SEQ - 1 - s) : s;
            size_t ro = (size_t)((bb << 12) + l) * DMODEL + d;
            float dtv = dtp[ro], xv = __bfloat162float(xp[ro]);
            sd += dtv;
            float dx = dtv * xv;
            #pragma unroll
            for (int n = 0; n < NSTATE; n++) {
                float e = __expf(dtv * an[n]);
                h[n] = e * h[n] + dx * Bsm[i * NSTATE + n];
            }
        }
    }
    size_t base = ((size_t)(bb * NCH + c) * DMODEL + d);
    #pragma unroll
    for (int n = 0; n < NSTATE; n++) g_hend[dir][base * NSTATE + n] = h[n];
    g_sumdt[dir][base] = sd;
}

__global__ void hm_scanB_kernel(const float* __restrict__ A_log0,
                                const float* __restrict__ A_log1) {
    int dir = blockIdx.x >> 1, bb = blockIdx.x & 1;
    int t = threadIdx.x;
    for (int tn = t; tn < DMODEL * NSTATE; tn += blockDim.x) {
        int d = tn >> 4, n = tn & 15;
        const float* A_log = dir ? A_log1 : A_log0;
        float an = -__expf(A_log[d * NSTATE + n]);
        float h = 0.f;
        for (int c = 0; c < NCH; c++) {
            size_t base = ((size_t)(bb * NCH + c) * DMODEL + d);
            g_hinit[dir][base * NSTATE + n] = h;
            float sd = g_sumdt[dir][base];
            h = __expf(sd * an) * h + g_hend[dir][base * NSTATE + n];
        }
    }
}

__global__ void hm_scanC_kernel(const float* __restrict__ A_log0,
                                const float* __restrict__ A_log1,
                                const float* __restrict__ D0,
                                const float* __restrict__ D1) {
    int c = blockIdx.x;
    int dir = blockIdx.y >> 1, bb = blockIdx.y & 1;
    int d = threadIdx.x;                  // 192
    __shared__ float Bsm[CSZ * NSTATE];
    __shared__ float Csm[CSZ * NSTATE];
    const float* xdbl = g_xdbl[dir];
    for (int idx = d; idx < CSZ * NSTATE; idx += DMODEL) {
        int i = idx >> 4, n = idx & 15;
        int s = c * CSZ + i;
        int l = dir ? (L_SEQ - 1 - s) : s;
        size_t ro = (size_t)((bb << 12) + l) * 44;
        Bsm[idx] = xdbl[ro + 12 + n];
        Csm[idx] = xdbl[ro + 28 + n];
    }
    __syncthreads();
    const float* A_log = dir ? A_log1 : A_log0;
    const float* Dp = dir ? D1 : D0;
    float an[NSTATE];
    bool fast = true;
    #pragma unroll
    for (int n = 0; n < NSTATE; n++) {
        an[n] = -__expf(A_log[d * NSTATE + n]);
        fast = fast && (fabsf(an[n] + (float)(n + 1)) < 1e-3f * (n + 1));
    }
    float h[NSTATE];
    size_t base = ((size_t)(bb * NCH + c) * DMODEL + d);
    #pragma unroll
    for (int n = 0; n < NSTATE; n++) h[n] = g_hinit[dir][base * NSTATE + n];
    float Dd = Dp[d];
    const float* dtp = g_dt[dir];
    const __nv_bfloat16* xp = g_xmc_bf[dir];
    if (fast) {
        for (int i = 0; i < CSZ; i++) {
            int s = c * CSZ + i;
            int l = dir ? (L_SEQ - 1 - s) : s;
            size_t row = (size_t)((bb << 12) + l);
            size_t ro = row * DMODEL + d;
            float dtv = dtp[ro], xv = __bfloat162float(xp[ro]);
            float dx = dtv * xv;
            float y = 0.f;
            float e1 = __expf(-dtv);
            float e2 = e1 * e1;
            float pa = e1, pb = e2;
            h[0] = pa * h[0] + dx * Bsm[i * NSTATE];
            h[1] = pb * h[1] + dx * Bsm[i * NSTATE + 1];
            y += h[0] * Csm[i * NSTATE] + h[1] * Csm[i * NSTATE + 1];
            #pragma unroll
            for (int n = 2; n < NSTATE; n += 2) {
                pa *= e2; pb *= e2;
                h[n]     = pa * h[n]     + dx * Bsm[i * NSTATE + n];
                h[n + 1] = pb * h[n + 1] + dx * Bsm[i * NSTATE + n + 1];
                y += h[n] * Csm[i * NSTATE + n] + h[n + 1] * Csm[i * NSTATE + n + 1];
            }
            float yf = y + Dd * xv;
            float zv = __bfloat162float(g_xz_bf[row * 768 + dir * 384 + DMODEL + d]);
            g_yg_bf[row * 384 + dir * DMODEL + d] =
                __float2bfloat16(yf * zv * sigmoidf_(zv));
        }
    } else {
        for (int i = 0; i < CSZ; i++) {
            int s = c * CSZ + i;
            int l = dir ? (L_SEQ - 1 - s) : s;
            size_t row = (size_t)((bb << 12) + l);
            size_t ro = row * DMODEL + d;
            float dtv = dtp[ro], xv = __bfloat162float(xp[ro]);
            float dx = dtv * xv;
            float y = 0.f;
            #pragma unroll
            for (int n = 0; n < NSTATE; n++) {
                float e = __expf(dtv * an[n]);
                h[n] = e * h[n] + dx * Bsm[i * NSTATE + n];
                y += h[n] * Csm[i * NSTATE + n];
            }
            float yf = y + Dd * xv;
            float zv = __bfloat162float(g_xz_bf[row * 768 + dir * 384 + DMODEL + d]);
            g_yg_bf[row * 384 + dir * DMODEL + d] =
                __float2bfloat16(yf * zv * sigmoidf_(zv));
        }
    }
}

// ---------------- depthwise 3x3 conv + gate (8 px/block) ------------------------
__global__ void __launch_bounds__(384)
hm_dwconv_kernel(const float* __restrict__ dww,
                 const float* __restrict__ dwb) {
    int p0 = blockIdx.x * 8;
    int bb = p0 >> 12, hw = p0 & 4095, h = hw >> 6, w0 = hw & 63;
    int c = threadIdx.x;                  // 384
    float b1 = dwb[c], b2 = dwb[c + 384];
    float a1[8], a2[8];
    #pragma unroll
    for (int j = 0; j < 8; j++) { a1[j] = b1; a2[j] = b2; }
    #pragma unroll
    for (int di = 0; di < 3; di++) {
        int hh = h + di - 1;
        if (hh < 0 || hh > 63) continue;
        float wA0 = dww[c * 9 + di * 3],     wA1 = dww[c * 9 + di * 3 + 1],
              wA2 = dww[c * 9 + di * 3 + 2];
        float wB0 = dww[(c + 384) * 9 + di * 3],     wB1 = dww[(c + 384) * 9 + di * 3 + 1],
              wB2 = dww[(c + 384) * 9 + di * 3 + 2];
        #pragma unroll
        for (int dwp = 0; dwp < 10; dwp++) {
            int ww = w0 + dwp - 1;
            if (ww < 0 || ww > 63) continue;
            size_t r = (size_t)((bb << 12) + (hh << 6) + ww) * 768;
            float v1 = __bfloat162float(g_t_bf[r + c]);
            float v2 = __bfloat162float(g_t_bf[r + 384 + c]);
            int j;
            j = dwp;     if (j < 8)           { a1[j] += v1 * wA0; a2[j] += v2 * wB0; }
            j = dwp - 1; if (j >= 0 && j < 8) { a1[j] += v1 * wA1; a2[j] += v2 * wB1; }
            j = dwp - 2; if (j >= 0)          { a1[j] += v1 * wA2; a2[j] += v2 * wB2; }
        }
    }
    #pragma unroll
    for (int j = 0; j < 8; j++)
        g_g_bf[(size_t)(p0 + j) * 384 + c] = __float2bfloat16(a1[j] * sigmoidf_(a2[j]));
}

// ---------------- final residual (BHWC -> NCHW, transposed tiles) ---------------
__global__ void __launch_bounds__(256)
hm_final_kernel(const float* __restrict__ x,
                const float* __restrict__ scale,
                const float* __restrict__ gamma,
                float* __restrict__ out) {
    __shared__ float t1[32][33];
    int c0 = blockIdx.x * 32, l0 = blockIdx.y * 32, bb = blockIdx.z;
    int tc = threadIdx.x & 31, tr = threadIdx.x >> 5;
    float g = *gamma, s = *scale;
    for (int lr = tr; lr < 32; lr += 8) {
        size_t ri = (size_t)((bb << 12) + l0 + lr) * DMODEL + c0 + tc;
        t1[tc][lr] = s * g_mo[ri] + g_sg[ri];
    }
    __syncthreads();
    for (int cr = tr; cr < 32; cr += 8) {
        size_t oi = ((size_t)(bb * DMODEL + c0 + cr) << 12) + l0 + tc;
        out[oi] = x[oi] + g * t1[cr][tc];
    }
}

// ---------------- host side ------------------------------------------------------
extern "C" void kernel_launch(void* const* d_in, const int* in_sizes, int n_in,
                              void* d_out, int out_size) {
    (void)n_in; (void)out_size;

    const float *x, *ln_w, *ln_b, *scale_m, *c1w, *c1b, *dww, *dwb, *c2w, *c2b, *gamma;
    const float *in_w0, *conv_w0, *conv_b0, *xproj_w0, *dt_w0, *dt_b0, *A_log0, *D0, *out_w0;
    const float *in_w1, *conv_w1, *conv_b1, *xproj_w1, *dt_w1, *dt_b1, *A_log1, *D1, *out_w1;

    x    = (const float*)d_in[0];
    ln_w = (const float*)d_in[1];
    ln_b = (const float*)d_in[2];
    if (in_sizes[3] == 1) {
        scale_m = (const float*)d_in[3];
        c1w     = (const float*)d_in[4];
        c1b     = (const float*)d_in[5];
        dww     = (const float*)d_in[6];
        dwb     = (const float*)d_in[7];
        c2w     = (const float*)d_in[8];
        c2b     = (const float*)d_in[9];
        gamma   = (const float*)d_in[10];
        in_w0    = (const float*)d_in[11];
        conv_w0  = (const float*)d_in[12];
        conv_b0  = (const float*)d_in[13];
        xproj_w0 = (const float*)d_in[14];
        dt_w0    = (const float*)d_in[15];
        dt_b0    = (const float*)d_in[16];
        A_log0   = (const float*)d_in[17];
        D0       = (const float*)d_in[18];
        out_w0   = (const float*)d_in[19];
        in_w1    = (const float*)d_in[20];
        conv_w1  = (const float*)d_in[21];
        conv_b1  = (const float*)d_in[22];
        xproj_w1 = (const float*)d_in[23];
        dt_w1    = (const float*)d_in[24];
        dt_b1    = (const float*)d_in[25];
        A_log1   = (const float*)d_in[26];
        D1       = (const float*)d_in[27];
        out_w1   = (const float*)d_in[28];
    } else {
        in_w0    = (const float*)d_in[3];
        conv_w0  = (const float*)d_in[4];
        conv_b0  = (const float*)d_in[5];
        xproj_w0 = (const float*)d_in[6];
        dt_w0    = (const float*)d_in[7];
        dt_b0    = (const float*)d_in[8];
        A_log0   = (const float*)d_in[9];
        D0       = (const float*)d_in[10];
        out_w0   = (const float*)d_in[11];
        in_w1    = (const float*)d_in[12];
        conv_w1  = (const float*)d_in[13];
        conv_b1  = (const float*)d_in[14];
        xproj_w1 = (const float*)d_in[15];
        dt_w1    = (const float*)d_in[16];
        dt_b1    = (const float*)d_in[17];
        A_log1   = (const float*)d_in[18];
        D1       = (const float*)d_in[19];
        out_w1   = (const float*)d_in[20];
        scale_m  = (const float*)d_in[21];
        c1w      = (const float*)d_in[22];
        c1b      = (const float*)d_in[23];
        dww      = (const float*)d_in[24];
        dwb      = (const float*)d_in[25];
        c2w      = (const float*)d_in[26];
        c2b      = (const float*)d_in[27];
        gamma    = (const float*)d_in[28];
    }
    float* out = (float*)d_out;

    cudaFuncSetAttribute(hm_gemm_bf16, cudaFuncAttributeMaxDynamicSharedMemorySize, GSMEM);

    float *p_xdbl, *p_dt, *p_mo, *p_sg;
    __nv_bfloat16 *p_xf_bf, *p_xz_bf, *p_xmc_bf, *p_yg_bf, *p_mo_bf, *p_t_bf, *p_g_bf;
    __nv_bfloat16 *p_wb_in, *p_wb_xp, *p_wb_out, *p_wb_c1, *p_wb_c2;
    cudaGetSymbolAddress((void**)&p_xdbl,  g_xdbl);
    cudaGetSymbolAddress((void**)&p_dt,    g_dt);
    cudaGetSymbolAddress((void**)&p_mo,    g_mo);
    cudaGetSymbolAddress((void**)&p_sg,    g_sg);
    cudaGetSymbolAddress((void**)&p_xf_bf, g_xf_bf);
    cudaGetSymbolAddress((void**)&p_xz_bf, g_xz_bf);
    cudaGetSymbolAddress((void**)&p_xmc_bf,g_xmc_bf);
    cudaGetSymbolAddress((void**)&p_yg_bf, g_yg_bf);
    cudaGetSymbolAddress((void**)&p_mo_bf, g_mo_bf);
    cudaGetSymbolAddress((void**)&p_t_bf,  g_t_bf);
    cudaGetSymbolAddress((void**)&p_g_bf,  g_g_bf);
    cudaGetSymbolAddress((void**)&p_wb_in, wb_in);
    cudaGetSymbolAddress((void**)&p_wb_xp, wb_xp);
    cudaGetSymbolAddress((void**)&p_wb_out,wb_out);
    cudaGetSymbolAddress((void**)&p_wb_c1, wb_c1);
    cudaGetSymbolAddress((void**)&p_wb_c2, wb_c2);
    float* p_xdbl0 = p_xdbl;
    float* p_xdbl1 = p_xdbl + (size_t)NROWS * 44;
    __nv_bfloat16* p_xmc_bf0 = p_xmc_bf;
    __nv_bfloat16* p_xmc_bf1 = p_xmc_bf + (size_t)NROWS * DMODEL;
    float* p_dt0 = p_dt;
    float* p_dt1 = p_dt + (size_t)NROWS * DMODEL;

    // 1. pack weights -> bf16
    hm_pack_kernel<<<(PACK_TOTAL + 255) / 256, 256>>>(
        in_w0, in_w1, xproj_w0, xproj_w1, out_w0, out_w1, c1w, c2w);
    // 2. LayerNorm -> xf bf16
    hm_ln_kernel<<<dim3(128, 2), 256>>>(x, ln_w, ln_b);
    // 3. in_proj (N=768) -> xz bf16
    hm_gemm_bf16<<<dim3(12, 64, 1), 256, GSMEM>>>(
        p_xf_bf, p_wb_in, nullptr, nullptr, nullptr,
        nullptr, nullptr, nullptr, p_xz_bf, DMODEL, 768, 768, DMODEL);
    // 4. depthwise conv1d + silu -> xmc bf16 (2 rows/thread)
    hm_conv1d_kernel<<<NROWS / 2, 2 * DMODEL>>>(conv_w0, conv_b0, conv_w1, conv_b1);
    // 5. x_dbl projections (dual via z, N=44) -> fp32
    hm_gemm_bf16<<<dim3(1, 64, 2), 256, GSMEM>>>(
        p_xmc_bf0, p_wb_xp, p_xmc_bf1, p_wb_xp + 44 * 192, p_xdbl1,
        nullptr, nullptr, p_xdbl0, nullptr, DMODEL, 44, 44, DMODEL);
    // 6. dt = softplus(...) (K=12 SIMT, dual via z) -> fp32
    hm_dt_kernel<<<dim3(3, 128, 2), 256>>>(
        p_xdbl0, dt_w0, dt_b0, p_dt0, p_xdbl1, dt_w1, dt_b1, p_dt1);
    // 7-9. chunked selective scan
    hm_scanA_kernel<<<dim3(NCH, 4), DMODEL>>>(A_log0, A_log1);
    hm_scanB_kernel<<<4, 1024>>>(A_log0, A_log1);
    hm_scanC_kernel<<<dim3(NCH, 4), DMODEL>>>(A_log0, A_log1, D0, D1);
    // 10. out_proj (K=384): mo fp32 + bf16
    hm_gemm_bf16<<<dim3(3, 64, 1), 256, GSMEM>>>(
        p_yg_bf, p_wb_out, nullptr, nullptr, nullptr,
        nullptr, nullptr, p_mo, p_mo_bf, 384, DMODEL, DMODEL, 384);
    // 11. SGFN c1 -> t bf16 (scale + bias)
    hm_gemm_bf16<<<dim3(12, 64, 1), 256, GSMEM>>>(
        p_mo_bf, p_wb_c1, nullptr, nullptr, nullptr,
        c1b, scale_m, nullptr, p_t_bf, DMODEL, 768, 768, DMODEL);
    // 12. depthwise 3x3 + gate
    hm_dwconv_kernel<<<NROWS / 8, 384>>>(dww, dwb);
    // 13. c2 -> sg fp32
    hm_gemm_bf16<<<dim3(3, 64, 1), 256, GSMEM>>>(
        p_g_bf, p_wb_c2, nullptr, nullptr, nullptr,
        c2b, nullptr, p_sg, nullptr, 384, DMODEL, DMODEL, 384);
    // 14. residual + transpose to NCHW
    hm_final_kernel<<<dim3(6, 128, 2), 256>>>(x, scale_m, gamma, out);
}

// round 15
// speedup vs baseline: 1.0187x; 1.0187x over previous
#include <cuda_runtime.h>
#include <cuda_bf16.h>
#include <mma.h>
#include <math.h>

using namespace nvcuda;

#define L_SEQ   4096
#define NROWS   8192          // BSZ * L
#define DMODEL  192
#define NSTATE  16
#define NCH     64
#define CSZ     64

// ---------------- fp32 scratch ------------------------------------------------
__device__ float g_xdbl[2][NROWS * 44];           // dt(12)|B(16)|C(16)
__device__ float g_dt  [2][NROWS * DMODEL];
__device__ float g_hend [2][2 * NCH * DMODEL * NSTATE];
__device__ float g_sumdt[2][2 * NCH * DMODEL];
__device__ float g_hinit[2][2 * NCH * DMODEL * NSTATE];
__device__ float g_mo  [NROWS * DMODEL];          // mamba out fp32
__device__ float g_sg  [NROWS * DMODEL];          // SGFN out fp32

// ---------------- bf16 activations ---------------------------------------------
__device__ __nv_bfloat16 g_xf_bf [NROWS * DMODEL];
__device__ __nv_bfloat16 g_xz_bf [NROWS * 768];   // [xm0|z0|xm1|z1]
__device__ __nv_bfloat16 g_xmc_bf[2][NROWS * DMODEL];
__device__ __nv_bfloat16 g_yg_bf [NROWS * 384];
__device__ __nv_bfloat16 g_mo_bf [NROWS * DMODEL];
__device__ __nv_bfloat16 g_t_bf  [NROWS * 768];
__device__ __nv_bfloat16 g_g_bf  [NROWS * 384];

// ---------------- bf16 packed weights ------------------------------------------
__device__ __nv_bfloat16 wb_in  [768 * 192];      // [in_w0 ; in_w1] along N
__device__ __nv_bfloat16 wb_xp  [2 * 44 * 192];
__device__ __nv_bfloat16 wb_out [192 * 384];      // [out_w0 | out_w1] along K
__device__ __nv_bfloat16 wb_c1  [768 * 192];
__device__ __nv_bfloat16 wb_c2  [192 * 384];

__device__ __forceinline__ float sigmoidf_(float v) { return 1.f / (1.f + __expf(-v)); }

// ---------------- weight pack -> bf16 ------------------------------------------
#define PS1 147456
#define PS2 16896
#define PS3 73728
#define PS4 147456
#define PS5 73728
#define PACK_TOTAL (PS1 + PS2 + PS3 + PS4 + PS5)
__global__ void hm_pack_kernel(const float* __restrict__ in_w0, const float* __restrict__ in_w1,
                               const float* __restrict__ xp0, const float* __restrict__ xp1,
                               const float* __restrict__ ow0, const float* __restrict__ ow1,
                               const float* __restrict__ c1w, const float* __restrict__ c2w) {
    int i = blockIdx.x * 256 + threadIdx.x;
    if (i >= PACK_TOTAL) return;
    if (i < PS1) {
        int n = i / 192, k = i % 192;
        wb_in[i] = __float2bfloat16(n < 384 ? in_w0[n * 192 + k] : in_w1[(n - 384) * 192 + k]);
        return;
    }
    i -= PS1;
    if (i < PS2) {
        int z = i / (44 * 192), r = i % (44 * 192);
        wb_xp[i] = __float2bfloat16(z ? xp1[r] : xp0[r]);
        return;
    }
    i -= PS2;
    if (i < PS3) {
        int e = i / 384, k = i % 384;
        wb_out[i] = __float2bfloat16(k < 192 ? ow0[e * 192 + k] : ow1[e * 192 + k - 192]);
        return;
    }
    i -= PS3;
    if (i < PS4) { wb_c1[i] = __float2bfloat16(c1w[i]); return; }
    i -= PS4;
    wb_c2[i] = __float2bfloat16(c2w[i]);
}

// ---------------- LayerNorm over channels -> bf16 ------------------------------
__global__ void __launch_bounds__(256)
hm_ln_kernel(const float* __restrict__ x,
             const float* __restrict__ w,
             const float* __restrict__ b) {
    __shared__ float tile[DMODEL][33];
    __shared__ float mu_s[32], rs_s[32];
    int bb = blockIdx.y;
    int l0 = blockIdx.x * 32;
    int tl = threadIdx.x & 31, tg = threadIdx.x >> 5;
    for (int c = tg; c < DMODEL; c += 8)
        tile[c][tl] = x[((size_t)(bb * DMODEL + c) << 12) + l0 + tl];
    __syncthreads();
    int l = threadIdx.x >> 3, i = threadIdx.x & 7;
    float s = 0.f, q = 0.f;
    for (int c = i; c < DMODEL; c += 8) {
        float v = tile[c][l];
        s += v; q += v * v;
    }
    #pragma unroll
    for (int o = 4; o; o >>= 1) {
        s += __shfl_down_sync(0xffffffff, s, o, 8);
        q += __shfl_down_sync(0xffffffff, q, o, 8);
    }
    if (i == 0) {
        float mu = s * (1.f / DMODEL);
        float var = q * (1.f / DMODEL) - mu * mu;
        mu_s[l] = mu;
        rs_s[l] = rsqrtf(var + 1e-5f);
    }
    __syncthreads();
    for (int idx = threadIdx.x; idx < 32 * DMODEL; idx += 256) {
        int ll = idx / DMODEL, c = idx % DMODEL;
        float v = tile[c][ll];
        g_xf_bf[(size_t)((bb << 12) + l0 + ll) * DMODEL + c] =
            __float2bfloat16((v - mu_s[ll]) * rs_s[ll] * w[c] + b[c]);
    }
}

// ---------------- bf16 cp.async tensor-core GEMM (64x64, 4 CTAs/SM) ------------
#define GBM 64
#define GBN 64
#define GBK 64
#define GLD 72

__device__ __forceinline__ void cp16(void* dst, const void* src, int bytes) {
    unsigned d = (unsigned)__cvta_generic_to_shared(dst);
    asm volatile("cp.async.cg.shared.global [%0], [%1], 16, %2;" :: "r"(d), "l"(src), "r"(bytes));
}

__global__ void __launch_bounds__(128, 4)
hm_gemm_bf16(const __nv_bfloat16* __restrict__ A,
             const __nv_bfloat16* __restrict__ W,
             const __nv_bfloat16* __restrict__ Aalt,
             const __nv_bfloat16* __restrict__ Walt,
             float* __restrict__ Calt,
             const float* __restrict__ bias,
             const float* __restrict__ scale,
             float* __restrict__ C,
             __nv_bfloat16* __restrict__ Cb,
             int lda, int ldc, int N, int K) {
    __shared__ __align__(16) __nv_bfloat16 sm[2 * GBM * GLD + 2 * GBN * GLD];
    __nv_bfloat16* sA = sm;
    __nv_bfloat16* sB = sm + 2 * GBM * GLD;

    if (blockIdx.z) { A = Aalt; W = Walt; C = Calt; Cb = nullptr; }

    int tid = threadIdx.x;
    int wid = tid >> 5;
    int wr = wid >> 1, wc = wid & 1;
    int row0 = blockIdx.y * GBM;
    int n0 = blockIdx.x * GBN;

    wmma::fragment<wmma::accumulator, 16, 16, 16, float> fc[2][2];
    #pragma unroll
    for (int i = 0; i < 2; i++)
        #pragma unroll
        for (int j = 0; j < 2; j++)
            wmma::fill_fragment(fc[i][j], 0.f);

    int nk = K / GBK;
    {
        #pragma unroll
        for (int i = 0; i < 4; i++) {
            int idx = tid + i * 128;
            int r = idx >> 3, ch = (idx & 7) * 8;
            cp16(sA + r * GLD + ch, A + (size_t)(row0 + r) * lda + ch, 16);
        }
        #pragma unroll
        for (int i = 0; i < 4; i++) {
            int idx = tid + i * 128;
            int r = idx >> 3, ch = (idx & 7) * 8;
            int n = n0 + r;
            const __nv_bfloat16* src = W + (size_t)(n < N ? n : 0) * K + ch;
            cp16(sB + r * GLD + ch, src, n < N ? 16 : 0);
        }
        asm volatile("cp.async.commit_group;");
    }

    for (int kt = 0; kt < nk; kt++) {
        int cur = kt & 1;
        bool more = (kt + 1 < nk);
        if (more) {
            int nxt = cur ^ 1;
            int k0 = (kt + 1) * GBK;
            #pragma unroll
            for (int i = 0; i < 4; i++) {
                int idx = tid + i * 128;
                int r = idx >> 3, ch = (idx & 7) * 8;
                cp16(sA + nxt * GBM * GLD + r * GLD + ch,
                     A + (size_t)(row0 + r) * lda + k0 + ch, 16);
            }
            #pragma unroll
            for (int i = 0; i < 4; i++) {
                int idx = tid + i * 128;
                int r = idx >> 3, ch = (idx & 7) * 8;
                int n = n0 + r;
                const __nv_bfloat16* src = W + (size_t)(n < N ? n : 0) * K + k0 + ch;
                cp16(sB + nxt * GBN * GLD + r * GLD + ch, src, n < N ? 16 : 0);
            }
            asm volatile("cp.async.commit_group;");
            asm volatile("cp.async.wait_group 1;");
        } else {
            asm volatile("cp.async.wait_group 0;");
        }
        __syncthreads();
        const __nv_bfloat16* cA = sA + cur * GBM * GLD;
        const __nv_bfloat16* cB = sB + cur * GBN * GLD;
        #pragma unroll
        for (int ks = 0; ks < 4; ks++) {
            wmma::fragment<wmma::matrix_a, 16, 16, 16, __nv_bfloat16, wmma::row_major> fa[2];
            wmma::fragment<wmma::matrix_b, 16, 16, 16, __nv_bfloat16, wmma::col_major> fb[2];
            #pragma unroll
            for (int i = 0; i < 2; i++)
                wmma::load_matrix_sync(fa[i], cA + (wr * 32 + i * 16) * GLD + ks * 16, GLD);
            #pragma unroll
            for (int j = 0; j < 2; j++)
                wmma::load_matrix_sync(fb[j], cB + (wc * 32 + j * 16) * GLD + ks * 16, GLD);
            #pragma unroll
            for (int i = 0; i < 2; i++)
                #pragma unroll
                for (int j = 0; j < 2; j++)
                    wmma::mma_sync(fc[i][j], fa[i], fb[j], fc[i][j]);
        }
        __syncthreads();
    }

    float* stage = (float*)sm;
    #pragma unroll
    for (int i = 0; i < 2; i++)
        #pragma unroll
        for (int j = 0; j < 2; j++)
            wmma::store_matrix_sync(stage + (wr * 32 + i * 16) * 68 + wc * 32 + j * 16,
                                    fc[i][j], 68, wmma::mem_row_major);
    __syncthreads();
    float sc = scale ? *scale : 1.f;
    for (int e = tid; e < GBM * GBN; e += 128) {
        int m = e >> 6, n = e & 63;
        int col = n0 + n;
        if (col >= N) continue;
        float v = stage[m * 68 + n] * sc;
        if (bias) v += bias[col];
        size_t o = (size_t)(row0 + m) * ldc + col;
        if (C) C[o] = v;
        if (Cb) Cb[o] = __float2bfloat16(v);
    }
}

// ---------------- dt projection (K=12, SIMT, dual via z) ------------------------
__global__ void hm_dt_kernel(const float* __restrict__ A0, const float* __restrict__ W0,
                             const float* __restrict__ b0, float* __restrict__ C0,
                             const float* __restrict__ A1, const float* __restrict__ W1,
                             const float* __restrict__ b1, float* __restrict__ C1) {
    const float* A = blockIdx.z ? A1 : A0;
    const float* W = blockIdx.z ? W1 : W0;
    const float* bias = blockIdx.z ? b1 : b0;
    float* C = blockIdx.z ? C1 : C0;
    const int lda = 44, ldc = DMODEL, N = DMODEL, K = 12;
    __shared__ float As[16][65];
    __shared__ float Ws[16][65];
    int tid = threadIdx.x;
    int tx = tid & 15, ty = tid >> 4;
    int row0 = blockIdx.y * 64;
    int n0 = blockIdx.x * 64;
    float acc[4][4] = {};
    {
        #pragma unroll
        for (int i = 0; i < 4; i++) {
            int li = tid + i * 256;
            int m = li >> 4, k = li & 15;
            As[k][m] = (k < K) ? A[(size_t)(row0 + m) * lda + k] : 0.f;
            int wrow = n0 + m;
            Ws[k][m] = (wrow < N && k < K) ? W[(size_t)wrow * K + k] : 0.f;
        }
        __syncthreads();
        #pragma unroll
        for (int kk = 0; kk < 12; kk++) {
            float a[4], w[4];
            #pragma unroll
            for (int i = 0; i < 4; i++) a[i] = As[kk][ty * 4 + i];
            #pragma unroll
            for (int j = 0; j < 4; j++) w[j] = Ws[kk][tx * 4 + j];
            #pragma unroll
            for (int i = 0; i < 4; i++)
                #pragma unroll
                for (int j = 0; j < 4; j++)
                    acc[i][j] += a[i] * w[j];
        }
    }
    #pragma unroll
    for (int i = 0; i < 4; i++) {
        #pragma unroll
        for (int j = 0; j < 4; j++) {
            int col = n0 + tx * 4 + j;
            if (col >= N) continue;
            float v = acc[i][j] + bias[col];
            v = (v > 20.f) ? v : log1pf(__expf(v));
            C[(size_t)(row0 + ty * 4 + i) * ldc + col] = v;
        }
    }
}

// ---------------- conv1d + silu, 2 rows/thread sliding window -------------------
__global__ void hm_conv1d_kernel(const float* __restrict__ cw0, const float* __restrict__ cb0,
                                 const float* __restrict__ cw1, const float* __restrict__ cb1) {
    int pr = blockIdx.x;                  // 4096 blocks
    int bb = pr >> 11, l0 = (pr & 2047) << 1;   // rows l0, l0+1
    int t = threadIdx.x;                  // 384
    int d = t % DMODEL, dir = t / DMODEL;
    const float* cw = dir ? cw1 : cw0;
    float w0 = cw[d * 4], w1 = cw[d * 4 + 1], w2 = cw[d * 4 + 2], w3 = cw[d * 4 + 3];
    float bv = dir ? cb1[d] : cb0[d];
    int col = dir * 384 + d;
    float v[5];
    float a0, a1;
    if (!dir) {
        #pragma unroll
        for (int k = 0; k < 5; k++) {
            int ls = l0 - 3 + k;
            v[k] = (ls >= 0)
                ? __bfloat162float(g_xz_bf[(size_t)((bb << 12) + ls) * 768 + col]) : 0.f;
        }
        a0 = bv + w0 * v[0] + w1 * v[1] + w2 * v[2] + w3 * v[3];
        a1 = bv + w0 * v[1] + w1 * v[2] + w2 * v[3] + w3 * v[4];
    } else {
        #pragma unroll
        for (int k = 0; k < 5; k++) {
            int ls = l0 + k;
            v[k] = (ls < L_SEQ)
                ? __bfloat162float(g_xz_bf[(size_t)((bb << 12) + ls) * 768 + col]) : 0.f;
        }
        a0 = bv + w3 * v[0] + w2 * v[1] + w1 * v[2] + w0 * v[3];
        a1 = bv + w3 * v[1] + w2 * v[2] + w1 * v[3] + w0 * v[4];
    }
    size_t o = (size_t)((bb << 12) + l0) * DMODEL + d;
    g_xmc_bf[dir][o] = __float2bfloat16(a0 * sigmoidf_(a0));
    g_xmc_bf[dir][o + DMODEL] = __float2bfloat16(a1 * sigmoidf_(a1));
}

// ---------------- chunked selective scan ----------------------------------------
__global__ void hm_scanA_kernel(const float* __restrict__ A_log0,
                                const float* __restrict__ A_log1) {
    int c = blockIdx.x;
    int dir = blockIdx.y >> 1, bb = blockIdx.y & 1;
    int d = threadIdx.x;                  // 192
    __shared__ float Bsm[CSZ * NSTATE];
    const float* xdbl = g_xdbl[dir];
    for (int idx = d; idx < CSZ * NSTATE; idx += DMODEL) {
        int i = idx >> 4, n = idx & 15;
        int s = c * CSZ + i;
        int l = dir ? (L_SEQ - 1 - s) : s;
        Bsm[idx] = xdbl[(size_t)((bb << 12) + l) * 44 + 12 + n];
    }
    __syncthreads();
    const float* A_log = dir ? A_log1 : A_log0;
    float an[NSTATE];
    bool fast = true;
    #pragma unroll
    for (int n = 0; n < NSTATE; n++) {
        an[n] = -__expf(A_log[d * NSTATE + n]);
        fast = fast && (fabsf(an[n] + (float)(n + 1)) < 1e-3f * (n + 1));
    }
    float h[NSTATE];
    #pragma unroll
    for (int n = 0; n < NSTATE; n++) h[n] = 0.f;
    float sd = 0.f;
    const float* dtp = g_dt[dir];
    const __nv_bfloat16* xp = g_xmc_bf[dir];
    if (fast) {
        for (int i = 0; i < CSZ; i++) {
            int s = c * CSZ + i;
            int l = dir ? (L_SEQ - 1 - s) : s;
            size_t ro = (size_t)((bb << 12) + l) * DMODEL + d;
            float dtv = dtp[ro], xv = __bfloat162float(xp[ro]);
            sd += dtv;
            float dx = dtv * xv;
            float e1 = __expf(-dtv);
            float e2 = e1 * e1;
            float pa = e1, pb = e2;
            h[0] = pa * h[0] + dx * Bsm[i * NSTATE];
            h[1] = pb * h[1] + dx * Bsm[i * NSTATE + 1];
            #pragma unroll
            for (int n = 2; n < NSTATE; n += 2) {
                pa *= e2; pb *= e2;
                h[n]     = pa * h[n]     + dx * Bsm[i * NSTATE + n];
                h[n + 1] = pb * h[n + 1] + dx * Bsm[i * NSTATE + n + 1];
            }
        }
    } else {
        for (int i = 0; i < CSZ; i++) {
            int s = c * CSZ + i;
            int l = dir ? (L_SEQ - 1 - s) : s;
            size_t ro = (size_t)((bb << 12) + l) * DMODEL + d;
            float dtv = dtp[ro], xv = __bfloat162float(xp[ro]);
            sd += dtv;
            float dx = dtv * xv;
            #pragma unroll
            for (int n = 0; n < NSTATE; n++) {
                float e = __expf(dtv * an[n]);
                h[n] = e * h[n] + dx * Bsm[i * NSTATE + n];
            }
        }
    }
    size_t base = ((size_t)(bb * NCH + c) * DMODEL + d);
    #pragma unroll
    for (int n = 0; n < NSTATE; n++) g_hend[dir][base * NSTATE + n] = h[n];
    g_sumdt[dir][base] = sd;
}

__global__ void hm_scanB_kernel(const float* __restrict__ A_log0,
                                const float* __restrict__ A_log1) {
    int dir = blockIdx.x >> 1, bb = blockIdx.x & 1;
    int t = threadIdx.x;
    for (int tn = t; tn < DMODEL * NSTATE; tn += blockDim.x) {
        int d = tn >> 4, n = tn & 15;
        const float* A_log = dir ? A_log1 : A_log0;
        float an = -__expf(A_log[d * NSTATE + n]);
        float h = 0.f;
        for (int c = 0; c < NCH; c++) {
            size_t base = ((size_t)(bb * NCH + c) * DMODEL + d);
            g_hinit[dir][base * NSTATE + n] = h;
            float sd = g_sumdt[dir][base];
            h = __expf(sd * an) * h + g_hend[dir][base * NSTATE + n];
        }
    }
}

__global__ void hm_scanC_kernel(const float* __restrict__ A_log0,
                                const float* __restrict__ A_log1,
                                const float* __restrict__ D0,
                                const float* __restrict__ D1) {
    int c = blockIdx.x;
    int dir = blockIdx.y >> 1, bb = blockIdx.y & 1;
    int d = threadIdx.x;                  // 192
    __shared__ float Bsm[CSZ * NSTATE];
    __shared__ float Csm[CSZ * NSTATE];
    const float* xdbl = g_xdbl[dir];
    for (int idx = d; idx < CSZ * NSTATE; idx += DMODEL) {
        int i = idx >> 4, n = idx & 15;
        int s = c * CSZ + i;
        int l = dir ? (L_SEQ - 1 - s) : s;
        size_t ro = (size_t)((bb << 12) + l) * 44;
        Bsm[idx] = xdbl[ro + 12 + n];
        Csm[idx] = xdbl[ro + 28 + n];
    }
    __syncthreads();
    const float* A_log = dir ? A_log1 : A_log0;
    const float* Dp = dir ? D1 : D0;
    float an[NSTATE];
    bool fast = true;
    #pragma unroll
    for (int n = 0; n < NSTATE; n++) {
        an[n] = -__expf(A_log[d * NSTATE + n]);
        fast = fast && (fabsf(an[n] + (float)(n + 1)) < 1e-3f * (n + 1));
    }
    float h[NSTATE];
    size_t base = ((size_t)(bb * NCH + c) * DMODEL + d);
    #pragma unroll
    for (int n = 0; n < NSTATE; n++) h[n] = g_hinit[dir][base * NSTATE + n];
    float Dd = Dp[d];
    const float* dtp = g_dt[dir];
    const __nv_bfloat16* xp = g_xmc_bf[dir];
    if (fast) {
        for (int i = 0; i < CSZ; i++) {
            int s = c * CSZ + i;
            int l = dir ? (L_SEQ - 1 - s) : s;
            size_t row = (size_t)((bb << 12) + l);
            size_t ro = row * DMODEL + d;
            float dtv = dtp[ro], xv = __bfloat162float(xp[ro]);
            float dx = dtv * xv;
            float y = 0.f;
            float e1 = __expf(-dtv);
            float e2 = e1 * e1;
            float pa = e1, pb = e2;
            h[0] = pa * h[0] + dx * Bsm[i * NSTATE];
            h[1] = pb * h[1] + dx * Bsm[i * NSTATE + 1];
            y += h[0] * Csm[i * NSTATE] + h[1] * Csm[i * NSTATE + 1];
            #pragma unroll
            for (int n = 2; n < NSTATE; n += 2) {
                pa *= e2; pb *= e2;
                h[n]     = pa * h[n]     + dx * Bsm[i * NSTATE + n];
                h[n + 1] = pb * h[n + 1] + dx * Bsm[i * NSTATE + n + 1];
                y += h[n] * Csm[i * NSTATE + n] + h[n + 1] * Csm[i * NSTATE + n + 1];
            }
            float yf = y + Dd * xv;
            float zv = __bfloat162float(g_xz_bf[row * 768 + dir * 384 + DMODEL + d]);
            g_yg_bf[row * 384 + dir * DMODEL + d] =
                __float2bfloat16(yf * zv * sigmoidf_(zv));
        }
    } else {
        for (int i = 0; i < CSZ; i++) {
            int s = c * CSZ + i;
            int l = dir ? (L_SEQ - 1 - s) : s;
            size_t row = (size_t)((bb << 12) + l);
            size_t ro = row * DMODEL + d;
            float dtv = dtp[ro], xv = __bfloat162float(xp[ro]);
            float dx = dtv * xv;
            float y = 0.f;
            #pragma unroll
            for (int n = 0; n < NSTATE; n++) {
                float e = __expf(dtv * an[n]);
                h[n] = e * h[n] + dx * Bsm[i * NSTATE + n];
                y += h[n] * Csm[i * NSTATE + n];
            }
            float yf = y + Dd * xv;
            float zv = __bfloat162float(g_xz_bf[row * 768 + dir * 384 + DMODEL + d]);
            g_yg_bf[row * 384 + dir * DMODEL + d] =
                __float2bfloat16(yf * zv * sigmoidf_(zv));
        }
    }
}

// ---------------- depthwise 3x3 conv + gate (8 px/block) ------------------------
__global__ void __launch_bounds__(384)
hm_dwconv_kernel(const float* __restrict__ dww,
                 const float* __restrict__ dwb) {
    int p0 = blockIdx.x * 8;
    int bb = p0 >> 12, hw = p0 & 4095, h = hw >> 6, w0 = hw & 63;
    int c = threadIdx.x;                  // 384
    float b1 = dwb[c], b2 = dwb[c + 384];
    float a1[8], a2[8];
    #pragma unroll
    for (int j = 0; j < 8; j++) { a1[j] = b1; a2[j] = b2; }
    #pragma unroll
    for (int di = 0; di < 3; di++) {
        int hh = h + di - 1;
        if (hh < 0 || hh > 63) continue;
        float wA0 = dww[c * 9 + di * 3],     wA1 = dww[c * 9 + di * 3 + 1],
              wA2 = dww[c * 9 + di * 3 + 2];
        float wB0 = dww[(c + 384) * 9 + di * 3],     wB1 = dww[(c + 384) * 9 + di * 3 + 1],
              wB2 = dww[(c + 384) * 9 + di * 3 + 2];
        #pragma unroll
        for (int dwp = 0; dwp < 10; dwp++) {
            int ww = w0 + dwp - 1;
            if (ww < 0 || ww > 63) continue;
            size_t r = (size_t)((bb << 12) + (hh << 6) + ww) * 768;
            float v1 = __bfloat162float(g_t_bf[r + c]);
            float v2 = __bfloat162float(g_t_bf[r + 384 + c]);
            int j;
            j = dwp;     if (j < 8)           { a1[j] += v1 * wA0; a2[j] += v2 * wB0; }
            j = dwp - 1; if (j >= 0 && j < 8) { a1[j] += v1 * wA1; a2[j] += v2 * wB1; }
            j = dwp - 2; if (j >= 0)          { a1[j] += v1 * wA2; a2[j] += v2 * wB2; }
        }
    }
    #pragma unroll
    for (int j = 0; j < 8; j++)
        g_g_bf[(size_t)(p0 + j) * 384 + c] = __float2bfloat16(a1[j] * sigmoidf_(a2[j]));
}

// ---------------- final residual (BHWC -> NCHW, transposed tiles) ---------------
__global__ void __launch_bounds__(256)
hm_final_kernel(const float* __restrict__ x,
                const float* __restrict__ scale,
                const float* __restrict__ gamma,
                float* __restrict__ out) {
    __shared__ float t1[32][33];
    int c0 = blockIdx.x * 32, l0 = blockIdx.y * 32, bb = blockIdx.z;
    int tc = threadIdx.x & 31, tr = threadIdx.x >> 5;
    float g = *gamma, s = *scale;
    for (int lr = tr; lr < 32; lr += 8) {
        size_t ri = (size_t)((bb << 12) + l0 + lr) * DMODEL + c0 + tc;
        t1[tc][lr] = s * g_mo[ri] + g_sg[ri];
    }
    __syncthreads();
    for (int cr = tr; cr < 32; cr += 8) {
        size_t oi = ((size_t)(bb * DMODEL + c0 + cr) << 12) + l0 + tc;
        out[oi] = x[oi] + g * t1[cr][tc];
    }
}

// ---------------- host side ------------------------------------------------------
extern "C" void kernel_launch(void* const* d_in, const int* in_sizes, int n_in,
                              void* d_out, int out_size) {
    (void)n_in; (void)out_size;

    const float *x, *ln_w, *ln_b, *scale_m, *c1w, *c1b, *dww, *dwb, *c2w, *c2b, *gamma;
    const float *in_w0, *conv_w0, *conv_b0, *xproj_w0, *dt_w0, *dt_b0, *A_log0, *D0, *out_w0;
    const float *in_w1, *conv_w1, *conv_b1, *xproj_w1, *dt_w1, *dt_b1, *A_log1, *D1, *out_w1;

    x    = (const float*)d_in[0];
    ln_w = (const float*)d_in[1];
    ln_b = (const float*)d_in[2];
    if (in_sizes[3] == 1) {
        scale_m = (const float*)d_in[3];
        c1w     = (const float*)d_in[4];
        c1b     = (const float*)d_in[5];
        dww     = (const float*)d_in[6];
        dwb     = (const float*)d_in[7];
        c2w     = (const float*)d_in[8];
        c2b     = (const float*)d_in[9];
        gamma   = (const float*)d_in[10];
        in_w0    = (const float*)d_in[11];
        conv_w0  = (const float*)d_in[12];
        conv_b0  = (const float*)d_in[13];
        xproj_w0 = (const float*)d_in[14];
        dt_w0    = (const float*)d_in[15];
        dt_b0    = (const float*)d_in[16];
        A_log0   = (const float*)d_in[17];
        D0       = (const float*)d_in[18];
        out_w0   = (const float*)d_in[19];
        in_w1    = (const float*)d_in[20];
        conv_w1  = (const float*)d_in[21];
        conv_b1  = (const float*)d_in[22];
        xproj_w1 = (const float*)d_in[23];
        dt_w1    = (const float*)d_in[24];
        dt_b1    = (const float*)d_in[25];
        A_log1   = (const float*)d_in[26];
        D1       = (const float*)d_in[27];
        out_w1   = (const float*)d_in[28];
    } else {
        in_w0    = (const float*)d_in[3];
        conv_w0  = (const float*)d_in[4];
        conv_b0  = (const float*)d_in[5];
        xproj_w0 = (const float*)d_in[6];
        dt_w0    = (const float*)d_in[7];
        dt_b0    = (const float*)d_in[8];
        A_log0   = (const float*)d_in[9];
        D0       = (const float*)d_in[10];
        out_w0   = (const float*)d_in[11];
        in_w1    = (const float*)d_in[12];
        conv_w1  = (const float*)d_in[13];
        conv_b1  = (const float*)d_in[14];
        xproj_w1 = (const float*)d_in[15];
        dt_w1    = (const float*)d_in[16];
        dt_b1    = (const float*)d_in[17];
        A_log1   = (const float*)d_in[18];
        D1       = (const float*)d_in[19];
        out_w1   = (const float*)d_in[20];
        scale_m  = (const float*)d_in[21];
        c1w      = (const float*)d_in[22];
        c1b      = (const float*)d_in[23];
        dww      = (const float*)d_in[24];
        dwb      = (const float*)d_in[25];
        c2w      = (const float*)d_in[26];
        c2b      = (const float*)d_in[27];
        gamma    = (const float*)d_in[28];
    }
    float* out = (float*)d_out;

    float *p_xdbl, *p_dt, *p_mo, *p_sg;
    __nv_bfloat16 *p_xf_bf, *p_xz_bf, *p_xmc_bf, *p_yg_bf, *p_mo_bf, *p_t_bf, *p_g_bf;
    __nv_bfloat16 *p_wb_in, *p_wb_xp, *p_wb_out, *p_wb_c1, *p_wb_c2;
    cudaGetSymbolAddress((void**)&p_xdbl,  g_xdbl);
    cudaGetSymbolAddress((void**)&p_dt,    g_dt);
    cudaGetSymbolAddress((void**)&p_mo,    g_mo);
    cudaGetSymbolAddress((void**)&p_sg,    g_sg);
    cudaGetSymbolAddress((void**)&p_xf_bf, g_xf_bf);
    cudaGetSymbolAddress((void**)&p_xz_bf, g_xz_bf);
    cudaGetSymbolAddress((void**)&p_xmc_bf,g_xmc_bf);
    cudaGetSymbolAddress((void**)&p_yg_bf, g_yg_bf);
    cudaGetSymbolAddress((void**)&p_mo_bf, g_mo_bf);
    cudaGetSymbolAddress((void**)&p_t_bf,  g_t_bf);
    cudaGetSymbolAddress((void**)&p_g_bf,  g_g_bf);
    cudaGetSymbolAddress((void**)&p_wb_in, wb_in);
    cudaGetSymbolAddress((void**)&p_wb_xp, wb_xp);
    cudaGetSymbolAddress((void**)&p_wb_out,wb_out);
    cudaGetSymbolAddress((void**)&p_wb_c1, wb_c1);
    cudaGetSymbolAddress((void**)&p_wb_c2, wb_c2);
    float* p_xdbl0 = p_xdbl;
    float* p_xdbl1 = p_xdbl + (size_t)NROWS * 44;
    __nv_bfloat16* p_xmc_bf0 = p_xmc_bf;
    __nv_bfloat16* p_xmc_bf1 = p_xmc_bf + (size_t)NROWS * DMODEL;
    float* p_dt0 = p_dt;
    float* p_dt1 = p_dt + (size_t)NROWS * DMODEL;

    // 1. pack weights -> bf16
    hm_pack_kernel<<<(PACK_TOTAL + 255) / 256, 256>>>(
        in_w0, in_w1, xproj_w0, xproj_w1, out_w0, out_w1, c1w, c2w);
    // 2. LayerNorm -> xf bf16
    hm_ln_kernel<<<dim3(128, 2), 256>>>(x, ln_w, ln_b);
    // 3. in_proj (N=768) -> xz bf16
    hm_gemm_bf16<<<dim3(12, 128, 1), 128>>>(
        p_xf_bf, p_wb_in, nullptr, nullptr, nullptr,
        nullptr, nullptr, nullptr, p_xz_bf, DMODEL, 768, 768, DMODEL);
    // 4. depthwise conv1d + silu -> xmc bf16 (2 rows/thread)
    hm_conv1d_kernel<<<NROWS / 2, 2 * DMODEL>>>(conv_w0, conv_b0, conv_w1, conv_b1);
    // 5. x_dbl projections (dual via z, N=44) -> fp32
    hm_gemm_bf16<<<dim3(1, 128, 2), 128>>>(
        p_xmc_bf0, p_wb_xp, p_xmc_bf1, p_wb_xp + 44 * 192, p_xdbl1,
        nullptr, nullptr, p_xdbl0, nullptr, DMODEL, 44, 44, DMODEL);
    // 6. dt = softplus(...) (K=12 SIMT, dual via z) -> fp32
    hm_dt_kernel<<<dim3(3, 128, 2), 256>>>(
        p_xdbl0, dt_w0, dt_b0, p_dt0, p_xdbl1, dt_w1, dt_b1, p_dt1);
    // 7-9. chunked selective scan
    hm_scanA_kernel<<<dim3(NCH, 4), DMODEL>>>(A_log0, A_log1);
    hm_scanB_kernel<<<4, 1024>>>(A_log0, A_log1);
    hm_scanC_kernel<<<dim3(NCH, 4), DMODEL>>>(A_log0, A_log1, D0, D1);
    // 10. out_proj (K=384): mo fp32 + bf16
    hm_gemm_bf16<<<dim3(3, 128, 1), 128>>>(
        p_yg_bf, p_wb_out, nullptr, nullptr, nullptr,
        nullptr, nullptr, p_mo, p_mo_bf, 384, DMODEL, DMODEL, 384);
    // 11. SGFN c1 -> t bf16 (scale + bias)
    hm_gemm_bf16<<<dim3(12, 128, 1), 128>>>(
        p_mo_bf, p_wb_c1, nullptr, nullptr, nullptr,
        c1b, scale_m, nullptr, p_t_bf, DMODEL, 768, 768, DMODEL);
    // 12. depthwise 3x3 + gate
    hm_dwconv_kernel<<<NROWS / 8, 384>>>(dww, dwb);
    // 13. c2 -> sg fp32
    hm_gemm_bf16<<<dim3(3, 128, 1), 128>>>(
        p_g_bf, p_wb_c2, nullptr, nullptr, nullptr,
        c2b, nullptr, p_sg, nullptr, 384, DMODEL, DMODEL, 384);
    // 14. residual + transpose to NCHW
    hm_final_kernel<<<dim3(6, 128, 2), 256>>>(x, scale_m, gamma, out);
}

// round 16
// speedup vs baseline: 1.0191x; 1.0004x over previous
#include <cuda_runtime.h>
#include <cuda_bf16.h>
#include <mma.h>
#include <math.h>

using namespace nvcuda;

#define L_SEQ   4096
#define NROWS   8192          // BSZ * L
#define DMODEL  192
#define NSTATE  16
#define NCH     64
#define CSZ     64

// ---------------- fp32 scratch ------------------------------------------------
__device__ float g_xdbl[2][NROWS * 44];           // dt(12)|B(16)|C(16)
__device__ float g_hend [2][2 * NCH * DMODEL * NSTATE];
__device__ float g_sumdt[2][2 * NCH * DMODEL];
__device__ float g_hinit[2][2 * NCH * DMODEL * NSTATE];
__device__ float g_mo  [NROWS * DMODEL];          // mamba out fp32
__device__ float g_sg  [NROWS * DMODEL];          // SGFN out fp32

// ---------------- bf16 activations ---------------------------------------------
__device__ __nv_bfloat16 g_xf_bf [NROWS * DMODEL];
__device__ __nv_bfloat16 g_xz_bf [NROWS * 768];   // [xm0|z0|xm1|z1]
__device__ __nv_bfloat16 g_xmc_bf[2][NROWS * DMODEL];
__device__ __nv_bfloat16 g_dt_bf [2][NROWS * DMODEL];
__device__ __nv_bfloat16 g_yg_bf [NROWS * 384];
__device__ __nv_bfloat16 g_mo_bf [NROWS * DMODEL];
__device__ __nv_bfloat16 g_t_bf  [NROWS * 768];
__device__ __nv_bfloat16 g_g_bf  [NROWS * 384];

// ---------------- bf16 packed weights ------------------------------------------
__device__ __nv_bfloat16 wb_in  [768 * 192];      // [in_w0 ; in_w1] along N
__device__ __nv_bfloat16 wb_xp  [2 * 44 * 192];
__device__ __nv_bfloat16 wb_out [192 * 384];      // [out_w0 | out_w1] along K
__device__ __nv_bfloat16 wb_c1  [768 * 192];
__device__ __nv_bfloat16 wb_c2  [192 * 384];

__device__ __forceinline__ float sigmoidf_(float v) { return 1.f / (1.f + __expf(-v)); }

// ---------------- weight pack -> bf16 ------------------------------------------
#define PS1 147456
#define PS2 16896
#define PS3 73728
#define PS4 147456
#define PS5 73728
#define PACK_TOTAL (PS1 + PS2 + PS3 + PS4 + PS5)
__global__ void hm_pack_kernel(const float* __restrict__ in_w0, const float* __restrict__ in_w1,
                               const float* __restrict__ xp0, const float* __restrict__ xp1,
                               const float* __restrict__ ow0, const float* __restrict__ ow1,
                               const float* __restrict__ c1w, const float* __restrict__ c2w) {
    int i = blockIdx.x * 256 + threadIdx.x;
    if (i >= PACK_TOTAL) return;
    if (i < PS1) {
        int n = i / 192, k = i % 192;
        wb_in[i] = __float2bfloat16(n < 384 ? in_w0[n * 192 + k] : in_w1[(n - 384) * 192 + k]);
        return;
    }
    i -= PS1;
    if (i < PS2) {
        int z = i / (44 * 192), r = i % (44 * 192);
        wb_xp[i] = __float2bfloat16(z ? xp1[r] : xp0[r]);
        return;
    }
    i -= PS2;
    if (i < PS3) {
        int e = i / 384, k = i % 384;
        wb_out[i] = __float2bfloat16(k < 192 ? ow0[e * 192 + k] : ow1[e * 192 + k - 192]);
        return;
    }
    i -= PS3;
    if (i < PS4) { wb_c1[i] = __float2bfloat16(c1w[i]); return; }
    i -= PS4;
    wb_c2[i] = __float2bfloat16(c2w[i]);
}

// ---------------- LayerNorm over channels -> bf16 ------------------------------
__global__ void __launch_bounds__(256)
hm_ln_kernel(const float* __restrict__ x,
             const float* __restrict__ w,
             const float* __restrict__ b) {
    __shared__ float tile[DMODEL][33];
    __shared__ float mu_s[32], rs_s[32];
    int bb = blockIdx.y;
    int l0 = blockIdx.x * 32;
    int tl = threadIdx.x & 31, tg = threadIdx.x >> 5;
    for (int c = tg; c < DMODEL; c += 8)
        tile[c][tl] = x[((size_t)(bb * DMODEL + c) << 12) + l0 + tl];
    __syncthreads();
    int l = threadIdx.x >> 3, i = threadIdx.x & 7;
    float s = 0.f, q = 0.f;
    for (int c = i; c < DMODEL; c += 8) {
        float v = tile[c][l];
        s += v; q += v * v;
    }
    #pragma unroll
    for (int o = 4; o; o >>= 1) {
        s += __shfl_down_sync(0xffffffff, s, o, 8);
        q += __shfl_down_sync(0xffffffff, q, o, 8);
    }
    if (i == 0) {
        float mu = s * (1.f / DMODEL);
        float var = q * (1.f / DMODEL) - mu * mu;
        mu_s[l] = mu;
        rs_s[l] = rsqrtf(var + 1e-5f);
    }
    __syncthreads();
    for (int idx = threadIdx.x; idx < 32 * DMODEL; idx += 256) {
        int ll = idx / DMODEL, c = idx % DMODEL;
        float v = tile[c][ll];
        g_xf_bf[(size_t)((bb << 12) + l0 + ll) * DMODEL + c] =
            __float2bfloat16((v - mu_s[ll]) * rs_s[ll] * w[c] + b[c]);
    }
}

// ---------------- bf16 cp.async tensor-core GEMM (64x64, 4 CTAs/SM) ------------
#define GBM 64
#define GBN 64
#define GBK 64
#define GLD 72

__device__ __forceinline__ void cp16(void* dst, const void* src, int bytes) {
    unsigned d = (unsigned)__cvta_generic_to_shared(dst);
    asm volatile("cp.async.cg.shared.global [%0], [%1], 16, %2;" :: "r"(d), "l"(src), "r"(bytes));
}

__global__ void __launch_bounds__(128, 4)
hm_gemm_bf16(const __nv_bfloat16* __restrict__ A,
             const __nv_bfloat16* __restrict__ W,
             const __nv_bfloat16* __restrict__ Aalt,
             const __nv_bfloat16* __restrict__ Walt,
             float* __restrict__ Calt,
             const float* __restrict__ bias,
             const float* __restrict__ scale,
             float* __restrict__ C,
             __nv_bfloat16* __restrict__ Cb,
             int lda, int ldc, int N, int K) {
    __shared__ __align__(16) __nv_bfloat16 sm[2 * GBM * GLD + 2 * GBN * GLD];
    __nv_bfloat16* sA = sm;
    __nv_bfloat16* sB = sm + 2 * GBM * GLD;

    if (blockIdx.z) { A = Aalt; W = Walt; C = Calt; Cb = nullptr; }

    int tid = threadIdx.x;
    int wid = tid >> 5;
    int wr = wid >> 1, wc = wid & 1;
    int row0 = blockIdx.y * GBM;
    int n0 = blockIdx.x * GBN;

    wmma::fragment<wmma::accumulator, 16, 16, 16, float> fc[2][2];
    #pragma unroll
    for (int i = 0; i < 2; i++)
        #pragma unroll
        for (int j = 0; j < 2; j++)
            wmma::fill_fragment(fc[i][j], 0.f);

    int nk = K / GBK;
    {
        #pragma unroll
        for (int i = 0; i < 4; i++) {
            int idx = tid + i * 128;
            int r = idx >> 3, ch = (idx & 7) * 8;
            cp16(sA + r * GLD + ch, A + (size_t)(row0 + r) * lda + ch, 16);
        }
        #pragma unroll
        for (int i = 0; i < 4; i++) {
            int idx = tid + i * 128;
            int r = idx >> 3, ch = (idx & 7) * 8;
            int n = n0 + r;
            const __nv_bfloat16* src = W + (size_t)(n < N ? n : 0) * K + ch;
            cp16(sB + r * GLD + ch, src, n < N ? 16 : 0);
        }
        asm volatile("cp.async.commit_group;");
    }

    for (int kt = 0; kt < nk; kt++) {
        int cur = kt & 1;
        bool more = (kt + 1 < nk);
        if (more) {
            int nxt = cur ^ 1;
            int k0 = (kt + 1) * GBK;
            #pragma unroll
            for (int i = 0; i < 4; i++) {
                int idx = tid + i * 128;
                int r = idx >> 3, ch = (idx & 7) * 8;
                cp16(sA + nxt * GBM * GLD + r * GLD + ch,
                     A + (size_t)(row0 + r) * lda + k0 + ch, 16);
            }
            #pragma unroll
            for (int i = 0; i < 4; i++) {
                int idx = tid + i * 128;
                int r = idx >> 3, ch = (idx & 7) * 8;
                int n = n0 + r;
                const __nv_bfloat16* src = W + (size_t)(n < N ? n : 0) * K + k0 + ch;
                cp16(sB + nxt * GBN * GLD + r * GLD + ch, src, n < N ? 16 : 0);
            }
            asm volatile("cp.async.commit_group;");
            asm volatile("cp.async.wait_group 1;");
        } else {
            asm volatile("cp.async.wait_group 0;");
        }
        __syncthreads();
        const __nv_bfloat16* cA = sA + cur * GBM * GLD;
        const __nv_bfloat16* cB = sB + cur * GBN * GLD;
        #pragma unroll
        for (int ks = 0; ks < 4; ks++) {
            wmma::fragment<wmma::matrix_a, 16, 16, 16, __nv_bfloat16, wmma::row_major> fa[2];
            wmma::fragment<wmma::matrix_b, 16, 16, 16, __nv_bfloat16, wmma::col_major> fb[2];
            #pragma unroll
            for (int i = 0; i < 2; i++)
                wmma::load_matrix_sync(fa[i], cA + (wr * 32 + i * 16) * GLD + ks * 16, GLD);
            #pragma unroll
            for (int j = 0; j < 2; j++)
                wmma::load_matrix_sync(fb[j], cB + (wc * 32 + j * 16) * GLD + ks * 16, GLD);
            #pragma unroll
            for (int i = 0; i < 2; i++)
                #pragma unroll
                for (int j = 0; j < 2; j++)
                    wmma::mma_sync(fc[i][j], fa[i], fb[j], fc[i][j]);
        }
        __syncthreads();
    }

    float* stage = (float*)sm;
    #pragma unroll
    for (int i = 0; i < 2; i++)
        #pragma unroll
        for (int j = 0; j < 2; j++)
            wmma::store_matrix_sync(stage + (wr * 32 + i * 16) * 68 + wc * 32 + j * 16,
                                    fc[i][j], 68, wmma::mem_row_major);
    __syncthreads();
    float sc = scale ? *scale : 1.f;
    for (int e = tid; e < GBM * GBN; e += 128) {
        int m = e >> 6, n = e & 63;
        int col = n0 + n;
        if (col >= N) continue;
        float v = stage[m * 68 + n] * sc;
        if (bias) v += bias[col];
        size_t o = (size_t)(row0 + m) * ldc + col;
        if (C) C[o] = v;
        if (Cb) Cb[o] = __float2bfloat16(v);
    }
}

// ---------------- dt projection (K=12, SIMT, dual via z) -> bf16 ----------------
__global__ void hm_dt_kernel(const float* __restrict__ A0, const float* __restrict__ W0,
                             const float* __restrict__ b0, __nv_bfloat16* __restrict__ C0,
                             const float* __restrict__ A1, const float* __restrict__ W1,
                             const float* __restrict__ b1, __nv_bfloat16* __restrict__ C1) {
    const float* A = blockIdx.z ? A1 : A0;
    const float* W = blockIdx.z ? W1 : W0;
    const float* bias = blockIdx.z ? b1 : b0;
    __nv_bfloat16* C = blockIdx.z ? C1 : C0;
    const int lda = 44, N = DMODEL, K = 12;
    __shared__ float As[16][65];
    __shared__ float Ws[16][65];
    int tid = threadIdx.x;
    int tx = tid & 15, ty = tid >> 4;
    int row0 = blockIdx.y * 64;
    int n0 = blockIdx.x * 64;
    float acc[4][4] = {};
    {
        #pragma unroll
        for (int i = 0; i < 4; i++) {
            int li = tid + i * 256;
            int m = li >> 4, k = li & 15;
            As[k][m] = (k < K) ? A[(size_t)(row0 + m) * lda + k] : 0.f;
            int wrow = n0 + m;
            Ws[k][m] = (wrow < N && k < K) ? W[(size_t)wrow * K + k] : 0.f;
        }
        __syncthreads();
        #pragma unroll
        for (int kk = 0; kk < 12; kk++) {
            float a[4], w[4];
            #pragma unroll
            for (int i = 0; i < 4; i++) a[i] = As[kk][ty * 4 + i];
            #pragma unroll
            for (int j = 0; j < 4; j++) w[j] = Ws[kk][tx * 4 + j];
            #pragma unroll
            for (int i = 0; i < 4; i++)
                #pragma unroll
                for (int j = 0; j < 4; j++)
                    acc[i][j] += a[i] * w[j];
        }
    }
    #pragma unroll
    for (int i = 0; i < 4; i++) {
        #pragma unroll
        for (int j = 0; j < 4; j++) {
            int col = n0 + tx * 4 + j;
            if (col >= N) continue;
            float v = acc[i][j] + bias[col];
            v = (v > 20.f) ? v : log1pf(__expf(v));
            C[(size_t)(row0 + ty * 4 + i) * DMODEL + col] = __float2bfloat16(v);
        }
    }
}

// ---------------- conv1d + silu, bf16x2 channel pairs, 2 rows/thread ------------
// grid 2048, block 384: rg = t/192 (row-pair within 4-row block), dir = (t%192)/96,
// cp = t%96 -> channels 2cp, 2cp+1.
__global__ void __launch_bounds__(384)
hm_conv1d_kernel(const float* __restrict__ cw0, const float* __restrict__ cb0,
                 const float* __restrict__ cw1, const float* __restrict__ cb1) {
    int pr = blockIdx.x;                  // 2048 blocks, 4 rows each
    int bb = pr >> 10, lbase = (pr & 1023) << 2;
    int t = threadIdx.x;
    int rg = t >> 7 >> 1;                 // not used; recompute cleanly below
    rg = t / 192;                         // 0,1
    int rem = t - rg * 192;
    int dir = rem / 96;
    int cp = rem - dir * 96;
    int c0 = cp * 2;
    int l0 = lbase + rg * 2;              // rows l0, l0+1
    const float* cw = dir ? cw1 : cw0;
    const float* cb = dir ? cb1 : cb0;
    float wx0 = cw[c0 * 4], wx1 = cw[c0 * 4 + 1], wx2 = cw[c0 * 4 + 2], wx3 = cw[c0 * 4 + 3];
    float wy0 = cw[c0 * 4 + 4], wy1 = cw[c0 * 4 + 5], wy2 = cw[c0 * 4 + 6], wy3 = cw[c0 * 4 + 7];
    float bx = cb[c0], by = cb[c0 + 1];
    int col = dir * 384 + c0;
    float2 v[5];
    #pragma unroll
    for (int k = 0; k < 5; k++) {
        int ls = dir ? (l0 + k) : (l0 - 3 + k);
        if (ls >= 0 && ls < L_SEQ) {
            __nv_bfloat162 p = *reinterpret_cast<const __nv_bfloat162*>(
                g_xz_bf + (size_t)((bb << 12) + ls) * 768 + col);
            v[k] = __bfloat1622float2(p);
        } else {
            v[k] = make_float2(0.f, 0.f);
        }
    }
    float ax0, ay0, ax1, ay1;
    if (!dir) {
        ax0 = bx + wx0 * v[0].x + wx1 * v[1].x + wx2 * v[2].x + wx3 * v[3].x;
        ay0 = by + wy0 * v[0].y + wy1 * v[1].y + wy2 * v[2].y + wy3 * v[3].y;
        ax1 = bx + wx0 * v[1].x + wx1 * v[2].x + wx2 * v[3].x + wx3 * v[4].x;
        ay1 = by + wy0 * v[1].y + wy1 * v[2].y + wy2 * v[3].y + wy3 * v[4].y;
    } else {
        ax0 = bx + wx3 * v[0].x + wx2 * v[1].x + wx1 * v[2].x + wx0 * v[3].x;
        ay0 = by + wy3 * v[0].y + wy2 * v[1].y + wy1 * v[2].y + wy0 * v[3].y;
        ax1 = bx + wx3 * v[1].x + wx2 * v[2].x + wx1 * v[3].x + wx0 * v[4].x;
        ay1 = by + wy3 * v[1].y + wy2 * v[2].y + wy1 * v[3].y + wy0 * v[4].y;
    }
    ax0 *= sigmoidf_(ax0); ay0 *= sigmoidf_(ay0);
    ax1 *= sigmoidf_(ax1); ay1 *= sigmoidf_(ay1);
    size_t o = (size_t)((bb << 12) + l0) * DMODEL + c0;
    *reinterpret_cast<__nv_bfloat162*>(g_xmc_bf[dir] + o) =
        __floats2bfloat162_rn(ax0, ay0);
    *reinterpret_cast<__nv_bfloat162*>(g_xmc_bf[dir] + o + DMODEL) =
        __floats2bfloat162_rn(ax1, ay1);
}

// ---------------- chunked selective scan ----------------------------------------
__global__ void hm_scanA_kernel(const float* __restrict__ A_log0,
                                const float* __restrict__ A_log1) {
    int c = blockIdx.x;
    int dir = blockIdx.y >> 1, bb = blockIdx.y & 1;
    int d = threadIdx.x;                  // 192
    __shared__ float Bsm[CSZ * NSTATE];
    const float* xdbl = g_xdbl[dir];
    for (int idx = d; idx < CSZ * NSTATE; idx += DMODEL) {
        int i = idx >> 4, n = idx & 15;
        int s = c * CSZ + i;
        int l = dir ? (L_SEQ - 1 - s) : s;
        Bsm[idx] = xdbl[(size_t)((bb << 12) + l) * 44 + 12 + n];
    }
    __syncthreads();
    const float* A_log = dir ? A_log1 : A_log0;
    float an[NSTATE];
    bool fast = true;
    #pragma unroll
    for (int n = 0; n < NSTATE; n++) {
        an[n] = -__expf(A_log[d * NSTATE + n]);
        fast = fast && (fabsf(an[n] + (float)(n + 1)) < 1e-3f * (n + 1));
    }
    float h[NSTATE];
    #pragma unroll
    for (int n = 0; n < NSTATE; n++) h[n] = 0.f;
    float sd = 0.f;
    const __nv_bfloat16* dtp = g_dt_bf[dir];
    const __nv_bfloat16* xp = g_xmc_bf[dir];
    if (fast) {
        for (int i = 0; i < CSZ; i++) {
            int s = c * CSZ + i;
            int l = dir ? (L_SEQ - 1 - s) : s;
            size_t ro = (size_t)((bb << 12) + l) * DMODEL + d;
            float dtv = __bfloat162float(dtp[ro]), xv = __bfloat162float(xp[ro]);
            sd += dtv;
            float dx = dtv * xv;
            float e1 = __expf(-dtv);
            float e2 = e1 * e1;
            float pa = e1, pb = e2;
            h[0] = pa * h[0] + dx * Bsm[i * NSTATE];
            h[1] = pb * h[1] + dx * Bsm[i * NSTATE + 1];
            #pragma unroll
            for (int n = 2; n < NSTATE; n += 2) {
                pa *= e2; pb *= e2;
                h[n]     = pa * h[n]     + dx * Bsm[i * NSTATE + n];
                h[n + 1] = pb * h[n + 1] + dx * Bsm[i * NSTATE + n + 1];
            }
        }
    } else {
        for (int i = 0; i < CSZ; i++) {
            int s = c * CSZ + i;
            int l = dir ? (L_SEQ - 1 - s) : s;
            size_t ro = (size_t)((bb << 12) + l) * DMODEL + d;
            float dtv = __bfloat162float(dtp[ro]), xv = __bfloat162float(xp[ro]);
            sd += dtv;
            float dx = dtv * xv;
            #pragma unroll
            for (int n = 0; n < NSTATE; n++) {
                float e = __expf(dtv * an[n]);
                h[n] = e * h[n] + dx * Bsm[i * NSTATE + n];
            }
        }
    }
    size_t base = ((size_t)(bb * NCH + c) * DMODEL + d);
    #pragma unroll
    for (int n = 0; n < NSTATE; n++) g_hend[dir][base * NSTATE + n] = h[n];
    g_sumdt[dir][base] = sd;
}

__global__ void hm_scanB_kernel(const float* __restrict__ A_log0,
                                const float* __restrict__ A_log1) {
    int dir = blockIdx.x >> 1, bb = blockIdx.x & 1;
    int t = threadIdx.x;
    for (int tn = t; tn < DMODEL * NSTATE; tn += blockDim.x) {
        int d = tn >> 4, n = tn & 15;
        const float* A_log = dir ? A_log1 : A_log0;
        float an = -__expf(A_log[d * NSTATE + n]);
        float h = 0.f;
        for (int c = 0; c < NCH; c++) {
            size_t base = ((size_t)(bb * NCH + c) * DMODEL + d);
            g_hinit[dir][base * NSTATE + n] = h;
            float sd = g_sumdt[dir][base];
            h = __expf(sd * an) * h + g_hend[dir][base * NSTATE + n];
        }
    }
}

__global__ void hm_scanC_kernel(const float* __restrict__ A_log0,
                                const float* __restrict__ A_log1,
                                const float* __restrict__ D0,
                                const float* __restrict__ D1) {
    int c = blockIdx.x;
    int dir = blockIdx.y >> 1, bb = blockIdx.y & 1;
    int d = threadIdx.x;                  // 192
    __shared__ float Bsm[CSZ * NSTATE];
    __shared__ float Csm[CSZ * NSTATE];
    const float* xdbl = g_xdbl[dir];
    for (int idx = d; idx < CSZ * NSTATE; idx += DMODEL) {
        int i = idx >> 4, n = idx & 15;
        int s = c * CSZ + i;
        int l = dir ? (L_SEQ - 1 - s) : s;
        size_t ro = (size_t)((bb << 12) + l) * 44;
        Bsm[idx] = xdbl[ro + 12 + n];
        Csm[idx] = xdbl[ro + 28 + n];
    }
    __syncthreads();
    const float* A_log = dir ? A_log1 : A_log0;
    const float* Dp = dir ? D1 : D0;
    float an[NSTATE];
    bool fast = true;
    #pragma unroll
    for (int n = 0; n < NSTATE; n++) {
        an[n] = -__expf(A_log[d * NSTATE + n]);
        fast = fast && (fabsf(an[n] + (float)(n + 1)) < 1e-3f * (n + 1));
    }
    float h[NSTATE];
    size_t base = ((size_t)(bb * NCH + c) * DMODEL + d);
    #pragma unroll
    for (int n = 0; n < NSTATE; n++) h[n] = g_hinit[dir][base * NSTATE + n];
    float Dd = Dp[d];
    const __nv_bfloat16* dtp = g_dt_bf[dir];
    const __nv_bfloat16* xp = g_xmc_bf[dir];
    if (fast) {
        for (int i = 0; i < CSZ; i++) {
            int s = c * CSZ + i;
            int l = dir ? (L_SEQ - 1 - s) : s;
            size_t row = (size_t)((bb << 12) + l);
            size_t ro = row * DMODEL + d;
            float dtv = __bfloat162float(dtp[ro]), xv = __bfloat162float(xp[ro]);
            float dx = dtv * xv;
            float y = 0.f;
            float e1 = __expf(-dtv);
            float e2 = e1 * e1;
            float pa = e1, pb = e2;
            h[0] = pa * h[0] + dx * Bsm[i * NSTATE];
            h[1] = pb * h[1] + dx * Bsm[i * NSTATE + 1];
            y += h[0] * Csm[i * NSTATE] + h[1] * Csm[i * NSTATE + 1];
            #pragma unroll
            for (int n = 2; n < NSTATE; n += 2) {
                pa *= e2; pb *= e2;
                h[n]     = pa * h[n]     + dx * Bsm[i * NSTATE + n];
                h[n + 1] = pb * h[n + 1] + dx * Bsm[i * NSTATE + n + 1];
                y += h[n] * Csm[i * NSTATE + n] + h[n + 1] * Csm[i * NSTATE + n + 1];
            }
            float yf = y + Dd * xv;
            float zv = __bfloat162float(g_xz_bf[row * 768 + dir * 384 + DMODEL + d]);
            g_yg_bf[row * 384 + dir * DMODEL + d] =
                __float2bfloat16(yf * zv * sigmoidf_(zv));
        }
    } else {
        for (int i = 0; i < CSZ; i++) {
            int s = c * CSZ + i;
            int l = dir ? (L_SEQ - 1 - s) : s;
            size_t row = (size_t)((bb << 12) + l);
            size_t ro = row * DMODEL + d;
            float dtv = __bfloat162float(dtp[ro]), xv = __bfloat162float(xp[ro]);
            float dx = dtv * xv;
            float y = 0.f;
            #pragma unroll
            for (int n = 0; n < NSTATE; n++) {
                float e = __expf(dtv * an[n]);
                h[n] = e * h[n] + dx * Bsm[i * NSTATE + n];
                y += h[n] * Csm[i * NSTATE + n];
            }
            float yf = y + Dd * xv;
            float zv = __bfloat162float(g_xz_bf[row * 768 + dir * 384 + DMODEL + d]);
            g_yg_bf[row * 384 + dir * DMODEL + d] =
                __float2bfloat16(yf * zv * sigmoidf_(zv));
        }
    }
}

// ---------------- depthwise 3x3 conv + gate (bf16x2 pairs, 8 px/block) ----------
__global__ void __launch_bounds__(192)
hm_dwconv_kernel(const float* __restrict__ dww,
                 const float* __restrict__ dwb) {
    int p0 = blockIdx.x * 8;
    int bb = p0 >> 12, hw = p0 & 4095, h = hw >> 6, w0 = hw & 63;
    int cp = threadIdx.x;                 // 192 channel pairs
    int c0 = cp * 2;
    float2 b1 = make_float2(dwb[c0], dwb[c0 + 1]);
    float2 b2 = make_float2(dwb[c0 + 384], dwb[c0 + 385]);
    float2 a1[8], a2[8];
    #pragma unroll
    for (int j = 0; j < 8; j++) { a1[j] = b1; a2[j] = b2; }
    #pragma unroll
    for (int di = 0; di < 3; di++) {
        int hh = h + di - 1;
        if (hh < 0 || hh > 63) continue;
        float wAx0 = dww[c0 * 9 + di * 3],       wAx1 = dww[c0 * 9 + di * 3 + 1],
              wAx2 = dww[c0 * 9 + di * 3 + 2];
        float wAy0 = dww[(c0 + 1) * 9 + di * 3], wAy1 = dww[(c0 + 1) * 9 + di * 3 + 1],
              wAy2 = dww[(c0 + 1) * 9 + di * 3 + 2];
        float wBx0 = dww[(c0 + 384) * 9 + di * 3], wBx1 = dww[(c0 + 384) * 9 + di * 3 + 1],
              wBx2 = dww[(c0 + 384) * 9 + di * 3 + 2];
        float wBy0 = dww[(c0 + 385) * 9 + di * 3], wBy1 = dww[(c0 + 385) * 9 + di * 3 + 1],
              wBy2 = dww[(c0 + 385) * 9 + di * 3 + 2];
        #pragma unroll
        for (int dwp = 0; dwp < 10; dwp++) {
            int ww = w0 + dwp - 1;
            if (ww < 0 || ww > 63) continue;
            size_t r = (size_t)((bb << 12) + (hh << 6) + ww) * 768;
            float2 v1 = __bfloat1622float2(
                *reinterpret_cast<const __nv_bfloat162*>(g_t_bf + r + c0));
            float2 v2 = __bfloat1622float2(
                *reinterpret_cast<const __nv_bfloat162*>(g_t_bf + r + 384 + c0));
            int j;
            j = dwp;
            if (j < 8) {
                a1[j].x += v1.x * wAx0; a1[j].y += v1.y * wAy0;
                a2[j].x += v2.x * wBx0; a2[j].y += v2.y * wBy0;
            }
            j = dwp - 1;
            if (j >= 0 && j < 8) {
                a1[j].x += v1.x * wAx1; a1[j].y += v1.y * wAy1;
                a2[j].x += v2.x * wBx1; a2[j].y += v2.y * wBy1;
            }
            j = dwp - 2;
            if (j >= 0) {
                a1[j].x += v1.x * wAx2; a1[j].y += v1.y * wAy2;
                a2[j].x += v2.x * wBx2; a2[j].y += v2.y * wBy2;
            }
        }
    }
    #pragma unroll
    for (int j = 0; j < 8; j++) {
        float gx = a1[j].x * sigmoidf_(a2[j].x);
        float gy = a1[j].y * sigmoidf_(a2[j].y);
        *reinterpret_cast<__nv_bfloat162*>(g_g_bf + (size_t)(p0 + j) * 384 + c0) =
            __floats2bfloat162_rn(gx, gy);
    }
}

// ---------------- final residual (BHWC -> NCHW, transposed tiles) ---------------
__global__ void __launch_bounds__(256)
hm_final_kernel(const float* __restrict__ x,
                const float* __restrict__ scale,
                const float* __restrict__ gamma,
                float* __restrict__ out) {
    __shared__ float t1[32][33];
    int c0 = blockIdx.x * 32, l0 = blockIdx.y * 32, bb = blockIdx.z;
    int tc = threadIdx.x & 31, tr = threadIdx.x >> 5;
    float g = *gamma, s = *scale;
    for (int lr = tr; lr < 32; lr += 8) {
        size_t ri = (size_t)((bb << 12) + l0 + lr) * DMODEL + c0 + tc;
        t1[tc][lr] = s * g_mo[ri] + g_sg[ri];
    }
    __syncthreads();
    for (int cr = tr; cr < 32; cr += 8) {
        size_t oi = ((size_t)(bb * DMODEL + c0 + cr) << 12) + l0 + tc;
        out[oi] = x[oi] + g * t1[cr][tc];
    }
}

// ---------------- host side ------------------------------------------------------
extern "C" void kernel_launch(void* const* d_in, const int* in_sizes, int n_in,
                              void* d_out, int out_size) {
    (void)n_in; (void)out_size;

    const float *x, *ln_w, *ln_b, *scale_m, *c1w, *c1b, *dww, *dwb, *c2w, *c2b, *gamma;
    const float *in_w0, *conv_w0, *conv_b0, *xproj_w0, *dt_w0, *dt_b0, *A_log0, *D0, *out_w0;
    const float *in_w1, *conv_w1, *conv_b1, *xproj_w1, *dt_w1, *dt_b1, *A_log1, *D1, *out_w1;

    x    = (const float*)d_in[0];
    ln_w = (const float*)d_in[1];
    ln_b = (const float*)d_in[2];
    if (in_sizes[3] == 1) {
        scale_m = (const float*)d_in[3];
        c1w     = (const float*)d_in[4];
        c1b     = (const float*)d_in[5];
        dww     = (const float*)d_in[6];
        dwb     = (const float*)d_in[7];
        c2w     = (const float*)d_in[8];
        c2b     = (const float*)d_in[9];
        gamma   = (const float*)d_in[10];
        in_w0    = (const float*)d_in[11];
        conv_w0  = (const float*)d_in[12];
        conv_b0  = (const float*)d_in[13];
        xproj_w0 = (const float*)d_in[14];
        dt_w0    = (const float*)d_in[15];
        dt_b0    = (const float*)d_in[16];
        A_log0   = (const float*)d_in[17];
        D0       = (const float*)d_in[18];
        out_w0   = (const float*)d_in[19];
        in_w1    = (const float*)d_in[20];
        conv_w1  = (const float*)d_in[21];
        conv_b1  = (const float*)d_in[22];
        xproj_w1 = (const float*)d_in[23];
        dt_w1    = (const float*)d_in[24];
        dt_b1    = (const float*)d_in[25];
        A_log1   = (const float*)d_in[26];
        D1       = (const float*)d_in[27];
        out_w1   = (const float*)d_in[28];
    } else {
        in_w0    = (const float*)d_in[3];
        conv_w0  = (const float*)d_in[4];
        conv_b0  = (const float*)d_in[5];
        xproj_w0 = (const float*)d_in[6];
        dt_w0    = (const float*)d_in[7];
        dt_b0    = (const float*)d_in[8];
        A_log0   = (const float*)d_in[9];
        D0       = (const float*)d_in[10];
        out_w0   = (const float*)d_in[11];
        in_w1    = (const float*)d_in[12];
        conv_w1  = (const float*)d_in[13];
        conv_b1  = (const float*)d_in[14];
        xproj_w1 = (const float*)d_in[15];
        dt_w1    = (const float*)d_in[16];
        dt_b1    = (const float*)d_in[17];
        A_log1   = (const float*)d_in[18];
        D1       = (const float*)d_in[19];
        out_w1   = (const float*)d_in[20];
        scale_m  = (const float*)d_in[21];
        c1w      = (const float*)d_in[22];
        c1b      = (const float*)d_in[23];
        dww      = (const float*)d_in[24];
        dwb      = (const float*)d_in[25];
        c2w      = (const float*)d_in[26];
        c2b      = (const float*)d_in[27];
        gamma    = (const float*)d_in[28];
    }
    float* out = (float*)d_out;

    float *p_xdbl, *p_mo, *p_sg;
    __nv_bfloat16 *p_xf_bf, *p_xz_bf, *p_xmc_bf, *p_dt_bf, *p_yg_bf, *p_mo_bf, *p_t_bf, *p_g_bf;
    __nv_bfloat16 *p_wb_in, *p_wb_xp, *p_wb_out, *p_wb_c1, *p_wb_c2;
    cudaGetSymbolAddress((void**)&p_xdbl,  g_xdbl);
    cudaGetSymbolAddress((void**)&p_mo,    g_mo);
    cudaGetSymbolAddress((void**)&p_sg,    g_sg);
    cudaGetSymbolAddress((void**)&p_xf_bf, g_xf_bf);
    cudaGetSymbolAddress((void**)&p_xz_bf, g_xz_bf);
    cudaGetSymbolAddress((void**)&p_xmc_bf,g_xmc_bf);
    cudaGetSymbolAddress((void**)&p_dt_bf, g_dt_bf);
    cudaGetSymbolAddress((void**)&p_yg_bf, g_yg_bf);
    cudaGetSymbolAddress((void**)&p_mo_bf, g_mo_bf);
    cudaGetSymbolAddress((void**)&p_t_bf,  g_t_bf);
    cudaGetSymbolAddress((void**)&p_g_bf,  g_g_bf);
    cudaGetSymbolAddress((void**)&p_wb_in, wb_in);
    cudaGetSymbolAddress((void**)&p_wb_xp, wb_xp);
    cudaGetSymbolAddress((void**)&p_wb_out,wb_out);
    cudaGetSymbolAddress((void**)&p_wb_c1, wb_c1);
    cudaGetSymbolAddress((void**)&p_wb_c2, wb_c2);
    float* p_xdbl0 = p_xdbl;
    float* p_xdbl1 = p_xdbl + (size_t)NROWS * 44;
    __nv_bfloat16* p_xmc_bf0 = p_xmc_bf;
    __nv_bfloat16* p_xmc_bf1 = p_xmc_bf + (size_t)NROWS * DMODEL;
    __nv_bfloat16* p_dt_bf0 = p_dt_bf;
    __nv_bfloat16* p_dt_bf1 = p_dt_bf + (size_t)NROWS * DMODEL;

    // 1. pack weights -> bf16
    hm_pack_kernel<<<(PACK_TOTAL + 255) / 256, 256>>>(
        in_w0, in_w1, xproj_w0, xproj_w1, out_w0, out_w1, c1w, c2w);
    // 2. LayerNorm -> xf bf16
    hm_ln_kernel<<<dim3(128, 2), 256>>>(x, ln_w, ln_b);
    // 3. in_proj (N=768) -> xz bf16
    hm_gemm_bf16<<<dim3(12, 128, 1), 128>>>(
        p_xf_bf, p_wb_in, nullptr, nullptr, nullptr,
        nullptr, nullptr, nullptr, p_xz_bf, DMODEL, 768, 768, DMODEL);
    // 4. depthwise conv1d + silu -> xmc bf16 (bf16x2 pairs)
    hm_conv1d_kernel<<<2048, 384>>>(conv_w0, conv_b0, conv_w1, conv_b1);
    // 5. x_dbl projections (dual via z, N=44) -> fp32
    hm_gemm_bf16<<<dim3(1, 128, 2), 128>>>(
        p_xmc_bf0, p_wb_xp, p_xmc_bf1, p_wb_xp + 44 * 192, p_xdbl1,
        nullptr, nullptr, p_xdbl0, nullptr, DMODEL, 44, 44, DMODEL);
    // 6. dt = softplus(...) (K=12 SIMT, dual via z) -> bf16
    hm_dt_kernel<<<dim3(3, 128, 2), 256>>>(
        p_xdbl0, dt_w0, dt_b0, p_dt_bf0, p_xdbl1, dt_w1, dt_b1, p_dt_bf1);
    // 7-9. chunked selective scan
    hm_scanA_kernel<<<dim3(NCH, 4), DMODEL>>>(A_log0, A_log1);
    hm_scanB_kernel<<<4, 1024>>>(A_log0, A_log1);
    hm_scanC_kernel<<<dim3(NCH, 4), DMODEL>>>(A_log0, A_log1, D0, D1);
    // 10. out_proj (K=384): mo fp32 + bf16
    hm_gemm_bf16<<<dim3(3, 128, 1), 128>>>(
        p_yg_bf, p_wb_out, nullptr, nullptr, nullptr,
        nullptr, nullptr, p_mo, p_mo_bf, 384, DMODEL, DMODEL, 384);
    // 11. SGFN c1 -> t bf16 (scale + bias)
    hm_gemm_bf16<<<dim3(12, 128, 1), 128>>>(
        p_mo_bf, p_wb_c1, nullptr, nullptr, nullptr,
        c1b, scale_m, nullptr, p_t_bf, DMODEL, 768, 768, DMODEL);
    // 12. depthwise 3x3 + gate (bf16x2 pairs)
    hm_dwconv_kernel<<<NROWS / 8, 192>>>(dww, dwb);
    // 13. c2 -> sg fp32
    hm_gemm_bf16<<<dim3(3, 128, 1), 128>>>(
        p_g_bf, p_wb_c2, nullptr, nullptr, nullptr,
        c2b, nullptr, p_sg, nullptr, 384, DMODEL, DMODEL, 384);
    // 14. residual + transpose to NCHW
    hm_final_kernel<<<dim3(6, 128, 2), 256>>>(x, scale_m, gamma, out);
}